// round 2
// baseline (speedup 1.0000x reference)
#include <cuda_runtime.h>
#include <cstdint>
#include <cstddef>

// Problem constants
#define MODEL_DIM 768
#define N_HEAD    12
#define HEAD_DIM  64
#define BATCH     2
#define SEQ       2048
#define ROWS_TOT  (BATCH * SEQ)          // 4096

// ---------------------------------------------------------------------------
// Scratch (no allocation allowed -> __device__ globals)
// ---------------------------------------------------------------------------
__device__ float g_qp[ROWS_TOT * MODEL_DIM];
__device__ float g_kp[ROWS_TOT * MODEL_DIM];
__device__ float g_vp[ROWS_TOT * MODEL_DIM];
__device__ float g_ctx[ROWS_TOT * MODEL_DIM];

// ---------------------------------------------------------------------------
// GEMM: C[M,768] = A[M,768] @ W[768,768]^T + bias   (torch Linear semantics)
// Tile 64x64x16, 256 threads, 4x4 register micro-tile per thread.
// Shared tiles stored k-major with row pad 68 -> conflict-free LDS.128.
// ---------------------------------------------------------------------------
__global__ __launch_bounds__(256) void gemm_bias_kernel(
    const float* __restrict__ A, const float* __restrict__ W,
    const float* __restrict__ bias, float* __restrict__ C) {
    __shared__ float As[16][68];   // As[k][m]
    __shared__ float Ws[16][68];   // Ws[k][n]

    const int tid = threadIdx.x;
    const int tx = tid & 15;          // n direction (0..15)
    const int ty = tid >> 4;          // m direction (0..15)
    const int bm = blockIdx.y * 64;
    const int bn = blockIdx.x * 64;

    const int lrow = tid >> 2;        // 0..63
    const int lk   = (tid & 3) << 2;  // 0,4,8,12

    const float* Arow = A + (size_t)(bm + lrow) * MODEL_DIM;
    const float* Wrow = W + (size_t)(bn + lrow) * MODEL_DIM;

    float acc[4][4] = {};

    for (int k0 = 0; k0 < MODEL_DIM; k0 += 16) {
        float4 av = *(const float4*)(Arow + k0 + lk);
        float4 wv = *(const float4*)(Wrow + k0 + lk);
        __syncthreads();
        As[lk + 0][lrow] = av.x; As[lk + 1][lrow] = av.y;
        As[lk + 2][lrow] = av.z; As[lk + 3][lrow] = av.w;
        Ws[lk + 0][lrow] = wv.x; Ws[lk + 1][lrow] = wv.y;
        Ws[lk + 2][lrow] = wv.z; Ws[lk + 3][lrow] = wv.w;
        __syncthreads();
#pragma unroll
        for (int k = 0; k < 16; k++) {
            float4 a = *(const float4*)&As[k][ty << 2];
            float4 b = *(const float4*)&Ws[k][tx << 2];
            float ar[4] = {a.x, a.y, a.z, a.w};
            float br[4] = {b.x, b.y, b.z, b.w};
#pragma unroll
            for (int i = 0; i < 4; i++)
#pragma unroll
                for (int j = 0; j < 4; j++)
                    acc[i][j] += ar[i] * br[j];
        }
    }

    float4 bv = *(const float4*)&bias[bn + (tx << 2)];
    float br[4] = {bv.x, bv.y, bv.z, bv.w};
#pragma unroll
    for (int i = 0; i < 4; i++) {
        float4 o;
        o.x = acc[i][0] + br[0];
        o.y = acc[i][1] + br[1];
        o.z = acc[i][2] + br[2];
        o.w = acc[i][3] + br[3];
        *(float4*)&C[(size_t)(bm + (ty << 2) + i) * MODEL_DIM + bn + (tx << 2)] = o;
    }
}

// ---------------------------------------------------------------------------
// Attention tile loaders
// src_base points at row 0 of the 64-row tile, row stride = MODEL_DIM,
// head slice already applied (64 contiguous floats per row).
// ---------------------------------------------------------------------------
__device__ __forceinline__ void load_tile_T(float* __restrict__ dst,
                                            const float* __restrict__ src_base,
                                            int tid) {
    // dst[d][r], row stride 68 (transposed)
    const int r  = tid >> 2;
    const int d0 = (tid & 3) << 4;
    const float* src = src_base + (size_t)r * MODEL_DIM + d0;
#pragma unroll
    for (int u = 0; u < 4; u++) {
        float4 v = *(const float4*)(src + u * 4);
        int d = d0 + u * 4;
        dst[(d + 0) * 68 + r] = v.x;
        dst[(d + 1) * 68 + r] = v.y;
        dst[(d + 2) * 68 + r] = v.z;
        dst[(d + 3) * 68 + r] = v.w;
    }
}

__device__ __forceinline__ void load_tile_N(float* __restrict__ dst,
                                            const float* __restrict__ src_base,
                                            int tid) {
    // dst[c][d], row stride 64 (natural)
    const int c  = tid >> 2;
    const int d0 = (tid & 3) << 4;
    const float* src = src_base + (size_t)c * MODEL_DIM + d0;
#pragma unroll
    for (int u = 0; u < 4; u++) {
        *(float4*)&dst[c * 64 + d0 + u * 4] = *(const float4*)(src + u * 4);
    }
}

// ---------------------------------------------------------------------------
// Attention kernel.
// grid = (S/64, H, B), 256 threads. Exact softmax in two passes over K:
//   pass 1: running row max + rescaled exp-sum
//   pass 2: recompute scores, write normalized weights to gmem (the required
//           attn_weights output) + smem, accumulate context = W @ V.
// ---------------------------------------------------------------------------
__global__ __launch_bounds__(256) void attn_kernel(
    const float* __restrict__ Qp, const float* __restrict__ Kp,
    const float* __restrict__ Vp, float* __restrict__ attn,
    float* __restrict__ ctx_out) {
    extern __shared__ float sm[];
    float* Qt = sm;               // [64 d][68] transposed Q tile
    float* Kt = Qt + 64 * 68;     // [64 d][68] transposed K chunk
    float* Vs = Kt + 64 * 68;     // [64 c][64 d] V chunk (natural)
    float* Ws = Vs + 64 * 64;     // [64 r][64 c] weight tile

    const int tid = threadIdx.x;
    const int tx = tid & 15;      // k-column / dim direction
    const int ty = tid >> 4;      // q-row direction
    const int b  = blockIdx.z;
    const int h  = blockIdx.y;
    const int q0 = blockIdx.x * 64;
    const float scale = 0.125f;   // 1/sqrt(64)

    const float* Qbase = Qp + ((size_t)(b * SEQ + q0)) * MODEL_DIM + h * HEAD_DIM;
    const float* Kbase0 = Kp + ((size_t)(b * SEQ)) * MODEL_DIM + h * HEAD_DIM;
    const float* Vbase0 = Vp + ((size_t)(b * SEQ)) * MODEL_DIM + h * HEAD_DIM;

    load_tile_T(Qt, Qbase, tid);

    float m_run[4], l_run[4];
#pragma unroll
    for (int i = 0; i < 4; i++) { m_run[i] = -1e30f; l_run[i] = 0.0f; }

    // ------------------- Pass 1: row max + exp-sum -------------------
    for (int kc = 0; kc < SEQ / 64; kc++) {
        __syncthreads();
        load_tile_T(Kt, Kbase0 + (size_t)(kc * 64) * MODEL_DIM, tid);
        __syncthreads();

        float s[4][4] = {};
#pragma unroll 4
        for (int d = 0; d < 64; d++) {
            float4 qa = *(const float4*)&Qt[d * 68 + (ty << 2)];
            float4 kb = *(const float4*)&Kt[d * 68 + (tx << 2)];
            float qr[4] = {qa.x, qa.y, qa.z, qa.w};
            float kr[4] = {kb.x, kb.y, kb.z, kb.w};
#pragma unroll
            for (int i = 0; i < 4; i++)
#pragma unroll
                for (int j = 0; j < 4; j++)
                    s[i][j] += qr[i] * kr[j];
        }
#pragma unroll
        for (int i = 0; i < 4; i++) {
#pragma unroll
            for (int j = 0; j < 4; j++) s[i][j] *= scale;
            float mx = fmaxf(fmaxf(s[i][0], s[i][1]), fmaxf(s[i][2], s[i][3]));
#pragma unroll
            for (int off = 1; off < 16; off <<= 1)
                mx = fmaxf(mx, __shfl_xor_sync(0xffffffffu, mx, off));
            float mn = fmaxf(m_run[i], mx);
            float p = __expf(s[i][0] - mn) + __expf(s[i][1] - mn) +
                      __expf(s[i][2] - mn) + __expf(s[i][3] - mn);
#pragma unroll
            for (int off = 1; off < 16; off <<= 1)
                p += __shfl_xor_sync(0xffffffffu, p, off);
            l_run[i] = l_run[i] * __expf(m_run[i] - mn) + p;
            m_run[i] = mn;
        }
    }

    float rinv[4];
#pragma unroll
    for (int i = 0; i < 4; i++) rinv[i] = 1.0f / l_run[i];

    // ------------------- Pass 2: weights + context -------------------
    float ctx[4][4] = {};
    const size_t attn_base = (((size_t)(b * N_HEAD + h)) * SEQ + q0) * SEQ;

    for (int kc = 0; kc < SEQ / 64; kc++) {
        const int c0 = kc * 64;
        __syncthreads();
        load_tile_T(Kt, Kbase0 + (size_t)c0 * MODEL_DIM, tid);
        load_tile_N(Vs, Vbase0 + (size_t)c0 * MODEL_DIM, tid);
        __syncthreads();

        float s[4][4] = {};
#pragma unroll 4
        for (int d = 0; d < 64; d++) {
            float4 qa = *(const float4*)&Qt[d * 68 + (ty << 2)];
            float4 kb = *(const float4*)&Kt[d * 68 + (tx << 2)];
            float qr[4] = {qa.x, qa.y, qa.z, qa.w};
            float kr[4] = {kb.x, kb.y, kb.z, kb.w};
#pragma unroll
            for (int i = 0; i < 4; i++)
#pragma unroll
                for (int j = 0; j < 4; j++)
                    s[i][j] += qr[i] * kr[j];
        }
#pragma unroll
        for (int i = 0; i < 4; i++) {
            float4 w;
            w.x = __expf(s[i][0] * scale - m_run[i]) * rinv[i];
            w.y = __expf(s[i][1] * scale - m_run[i]) * rinv[i];
            w.z = __expf(s[i][2] * scale - m_run[i]) * rinv[i];
            w.w = __expf(s[i][3] * scale - m_run[i]) * rinv[i];
            // required output: attn_weights[b][h][q][k]
            *(float4*)&attn[attn_base + (size_t)((ty << 2) + i) * SEQ + c0 + (tx << 2)] = w;
            // stage for context GEMM
            *(float4*)&Ws[((ty << 2) + i) * 64 + (tx << 2)] = w;
        }
        __syncthreads();
#pragma unroll 8
        for (int c = 0; c < 64; c++) {
            float wr[4];
#pragma unroll
            for (int i = 0; i < 4; i++) wr[i] = Ws[((ty << 2) + i) * 64 + c];
            float4 vv = *(const float4*)&Vs[c * 64 + (tx << 2)];
            float vr[4] = {vv.x, vv.y, vv.z, vv.w};
#pragma unroll
            for (int i = 0; i < 4; i++)
#pragma unroll
                for (int j = 0; j < 4; j++)
                    ctx[i][j] += wr[i] * vr[j];
        }
    }

    // store context laid out [B,S,MODEL_DIM] with this head's 64-col slice
#pragma unroll
    for (int i = 0; i < 4; i++) {
        float4 o;
        o.x = ctx[i][0]; o.y = ctx[i][1]; o.z = ctx[i][2]; o.w = ctx[i][3];
        *(float4*)&ctx_out[(size_t)(b * SEQ + q0 + (ty << 2) + i) * MODEL_DIM +
                           h * HEAD_DIM + (tx << 2)] = o;
    }
}

// ---------------------------------------------------------------------------
// Launch
// ---------------------------------------------------------------------------
extern "C" void kernel_launch(void* const* d_in, const int* in_sizes, int n_in,
                              void* d_out, int out_size) {
    const float* q    = (const float*)d_in[0];
    const float* k    = (const float*)d_in[1];
    const float* v    = (const float*)d_in[2];
    const float* wq_w = (const float*)d_in[3];
    const float* wq_b = (const float*)d_in[4];
    const float* wk_w = (const float*)d_in[5];
    const float* wk_b = (const float*)d_in[6];
    const float* wv_w = (const float*)d_in[7];
    const float* wv_b = (const float*)d_in[8];
    const float* wo_w = (const float*)d_in[9];
    const float* wo_b = (const float*)d_in[10];

    float *qp, *kp, *vp, *ctx;
    cudaGetSymbolAddress((void**)&qp,  g_qp);
    cudaGetSymbolAddress((void**)&kp,  g_kp);
    cudaGetSymbolAddress((void**)&vp,  g_vp);
    cudaGetSymbolAddress((void**)&ctx, g_ctx);

    float* out  = (float*)d_out;                              // [B,S,768]
    float* attn = out + (size_t)BATCH * SEQ * MODEL_DIM;      // [B,H,S,S]

    dim3 ggrid(MODEL_DIM / 64, ROWS_TOT / 64);                // (12, 64)
    gemm_bias_kernel<<<ggrid, 256>>>(q, wq_w, wq_b, qp);
    gemm_bias_kernel<<<ggrid, 256>>>(k, wk_w, wk_b, kp);
    gemm_bias_kernel<<<ggrid, 256>>>(v, wv_w, wv_b, vp);

    const int smem_bytes = (64 * 68 * 2 + 64 * 64 * 2) * (int)sizeof(float); // 67584
    cudaFuncSetAttribute(attn_kernel,
                         cudaFuncAttributeMaxDynamicSharedMemorySize, smem_bytes);
    attn_kernel<<<dim3(SEQ / 64, N_HEAD, BATCH), 256, smem_bytes>>>(qp, kp, vp, attn, ctx);

    gemm_bias_kernel<<<ggrid, 256>>>(ctx, wo_w, wo_b, out);
}

// round 3
// speedup vs baseline: 1.2619x; 1.2619x over previous
#include <cuda_runtime.h>
#include <cstdint>
#include <cstddef>

#define MODEL_DIM 768
#define N_HEAD    12
#define HEAD_DIM  64
#define BATCH     2
#define SEQ       2048
#define ROWS_TOT  (BATCH * SEQ)   // 4096

// ---------------------------------------------------------------------------
// Scratch (__device__ globals; no allocation allowed)
// ---------------------------------------------------------------------------
__device__ float g_qp[ROWS_TOT * MODEL_DIM];
__device__ float g_kp[ROWS_TOT * MODEL_DIM];
__device__ float g_vp[ROWS_TOT * MODEL_DIM];
__device__ float g_ctx[ROWS_TOT * MODEL_DIM];
__device__ float g_linv[BATCH * N_HEAD * SEQ];

// ---------------------------------------------------------------------------
// TF32 helpers
// ---------------------------------------------------------------------------
__device__ __forceinline__ uint32_t tf32_of(float x) {
    uint32_t u; asm("cvt.rna.tf32.f32 %0, %1;" : "=r"(u) : "f"(x)); return u;
}
__device__ __forceinline__ void split_tf32(float x, uint32_t& hi, uint32_t& lo) {
    hi = tf32_of(x);
    lo = tf32_of(x - __uint_as_float(hi));
}

// mma.m16n8k8 tf32: D += A*B
__device__ __forceinline__ void mma1(float* d, const uint4& a, const uint2& b) {
    asm volatile(
        "mma.sync.aligned.m16n8k8.row.col.f32.tf32.tf32.f32 "
        "{%0,%1,%2,%3},{%4,%5,%6,%7},{%8,%9},{%0,%1,%2,%3};"
        : "+f"(d[0]), "+f"(d[1]), "+f"(d[2]), "+f"(d[3])
        : "r"(a.x), "r"(a.y), "r"(a.z), "r"(a.w), "r"(b.x), "r"(b.y));
}
__device__ __forceinline__ void mma3(float* d, const uint4& ah, const uint4& al,
                                     const uint2& bh, const uint2& bl) {
    mma1(d, ah, bh); mma1(d, ah, bl); mma1(d, al, bh);
}

// Fragment-order smem indexing.
// A-operand region: 16x8 tiles, tile = 128 u32 (lane*4 + slot).
//   slot order: a0=(g,t) a1=(g+8,t) a2=(g,t+4) a3=(g+8,t+4)
__device__ __forceinline__ int a_off(int r, int c, int nkt) {
    return ((((r >> 4) * nkt + (c >> 3)) << 7) |
            (((((r & 7) << 2) | (c & 3)) << 2)) |
            (((r >> 3) & 1) | (((c >> 2) & 1) << 1)));
}
// B-operand region: 8x8 tiles (k x n), tile = 64 u32 (lane*2 + slot).
//   slot order: b0=(t,g) b1=(t+4,g)
__device__ __forceinline__ int b_off(int k, int n, int nkt) {
    return ((((n >> 3) * nkt + (k >> 3)) << 6) |
            (((((n & 7) << 2) | (k & 3)) << 1)) |
            ((k >> 2) & 1));
}

// ---------------------------------------------------------------------------
// Projection GEMM: C[4096,768] = A @ W^T + bias, 3xTF32.
// Block tile 128x128, KC=16, 8 warps (2m x 4n), warp tile 64x32.
// ---------------------------------------------------------------------------
__global__ __launch_bounds__(256) void proj3_kernel(
    const float* __restrict__ A, const float* __restrict__ W,
    const float* __restrict__ bias, float* __restrict__ C) {
    __shared__ uint32_t Ah[2048], Al[2048], Bh[2048], Bl[2048];

    const int tid = threadIdx.x;
    const int lane = tid & 31;
    const int w = tid >> 5;
    const int g = lane >> 2;
    const int t = lane & 3;
    const int bm = blockIdx.y * 128;
    const int bn = blockIdx.x * 128;
    const int m0 = (w >> 2) * 64;   // warp m offset
    const int n0 = (w & 3) * 32;    // warp n offset

    const int lrow = tid >> 1;             // 0..127
    const int lkb  = (tid & 1) * 8;        // 0 or 8

    const float* Asrc = A + (size_t)(bm + lrow) * MODEL_DIM + lkb;
    const float* Wsrc = W + (size_t)(bn + lrow) * MODEL_DIM + lkb;

    float acc[4][4][4] = {};
    float4 aR[2], wR[2];
    aR[0] = *(const float4*)(Asrc);     aR[1] = *(const float4*)(Asrc + 4);
    wR[0] = *(const float4*)(Wsrc);     wR[1] = *(const float4*)(Wsrc + 4);

    for (int it = 0; it < MODEL_DIM / 16; it++) {
        __syncthreads();
#pragma unroll
        for (int v = 0; v < 2; v++) {
            const float* fa = (const float*)&aR[v];
            const float* fw = (const float*)&wR[v];
#pragma unroll
            for (int e = 0; e < 4; e++) {
                int k = lkb + v * 4 + e;
                uint32_t hi, lo;
                split_tf32(fa[e], hi, lo);
                Ah[a_off(lrow, k, 2)] = hi; Al[a_off(lrow, k, 2)] = lo;
                split_tf32(fw[e], hi, lo);
                Bh[b_off(k, lrow, 2)] = hi; Bl[b_off(k, lrow, 2)] = lo;
            }
        }
        __syncthreads();
        if (it + 1 < MODEL_DIM / 16) {
            const float* An = Asrc + (it + 1) * 16;
            const float* Wn = Wsrc + (it + 1) * 16;
            aR[0] = *(const float4*)(An);     aR[1] = *(const float4*)(An + 4);
            wR[0] = *(const float4*)(Wn);     wR[1] = *(const float4*)(Wn + 4);
        }
#pragma unroll
        for (int kk = 0; kk < 2; kk++) {
            uint4 ah[4], al[4];
            uint2 bh[4], bl[4];
#pragma unroll
            for (int i = 0; i < 4; i++) {
                int ti = ((m0 >> 4) + i) * 2 + kk;
                ah[i] = ((const uint4*)Ah)[ti * 32 + lane];
                al[i] = ((const uint4*)Al)[ti * 32 + lane];
            }
#pragma unroll
            for (int j = 0; j < 4; j++) {
                int tj = ((n0 >> 3) + j) * 2 + kk;
                bh[j] = ((const uint2*)Bh)[tj * 32 + lane];
                bl[j] = ((const uint2*)Bl)[tj * 32 + lane];
            }
#pragma unroll
            for (int i = 0; i < 4; i++)
#pragma unroll
                for (int j = 0; j < 4; j++)
                    mma3(acc[i][j], ah[i], al[i], bh[j], bl[j]);
        }
    }

    // Epilogue with bias
#pragma unroll
    for (int j = 0; j < 4; j++) {
        int col = bn + n0 + j * 8 + t * 2;
        float b0 = __ldg(&bias[col]);
        float b1 = __ldg(&bias[col + 1]);
#pragma unroll
        for (int i = 0; i < 4; i++) {
            int r0 = bm + m0 + i * 16 + g;
            float2 o0 = {acc[i][j][0] + b0, acc[i][j][1] + b1};
            float2 o1 = {acc[i][j][2] + b0, acc[i][j][3] + b1};
            *(float2*)&C[(size_t)r0 * MODEL_DIM + col] = o0;
            *(float2*)&C[(size_t)(r0 + 8) * MODEL_DIM + col] = o1;
        }
    }
}

// ---------------------------------------------------------------------------
// Attention: single pass, unnormalized exp weights + l, 3xTF32 throughout.
// Block = (b, h, 128 q rows), 256 threads (8 warps: 4m x 2n), key chunks of 64.
// ---------------------------------------------------------------------------
#define QH_OFF 0
#define QL_OFF 8192
#define KH_OFF 16384
#define KL_OFF 20480
#define WH_OFF 24576
#define WL_OFF 32768
#define VH_OFF 40960
#define VL_OFF 45056
#define LS_OFF 49152
#define ATTN_SMEM ((49152 + 128) * 4)

__global__ __launch_bounds__(256, 1) void attn3_kernel(
    const float* __restrict__ Qp, const float* __restrict__ Kp,
    const float* __restrict__ Vp, float* __restrict__ attn,
    float* __restrict__ ctx_out, float* __restrict__ linv_out) {
    extern __shared__ uint32_t sm[];
    float* lsm = (float*)(sm + LS_OFF);

    const int tid = threadIdx.x;
    const int lane = tid & 31;
    const int w = tid >> 5;
    const int g = lane >> 2;
    const int t = lane & 3;
    const int b = blockIdx.z;
    const int h = blockIdx.y;
    const int q0 = blockIdx.x * 128;

    const int m0 = (w >> 1) * 32;   // warp rows (q), also ctx rows
    const int n0 = (w & 1) * 32;    // warp cols (keys for scores, d for ctx)

    // ---- load Q tile (scaled by 1/8) into A-frag hi/lo ----
    {
        int row = tid >> 1;
        int dbase = (tid & 1) * 32;
        const float* qsrc = Qp + (size_t)(b * SEQ + q0 + row) * MODEL_DIM + h * HEAD_DIM;
#pragma unroll
        for (int u = 0; u < 8; u++) {
            float4 f = *(const float4*)(qsrc + dbase + u * 4);
            const float* fe = (const float*)&f;
#pragma unroll
            for (int e = 0; e < 4; e++) {
                int d = dbase + u * 4 + e;
                uint32_t hi, lo;
                split_tf32(fe[e] * 0.125f, hi, lo);
                sm[QH_OFF + a_off(row, d, 8)] = hi;
                sm[QL_OFF + a_off(row, d, 8)] = lo;
            }
        }
    }
    if (tid < 128) lsm[tid] = 0.0f;

    float l_part[4] = {0.f, 0.f, 0.f, 0.f};
    float cacc[2][4][4] = {};

    const int key = tid >> 2;            // chunk loader row (0..63)
    const int kdb = (tid & 3) * 16;      // chunk loader d base

    for (int kc = 0; kc < SEQ / 64; kc++) {
        const int c0 = kc * 64;
        __syncthreads();
        // ---- load K, V chunk into B-frag hi/lo ----
        {
            const float* ksrc = Kp + (size_t)(b * SEQ + c0 + key) * MODEL_DIM + h * HEAD_DIM;
            const float* vsrc = Vp + (size_t)(b * SEQ + c0 + key) * MODEL_DIM + h * HEAD_DIM;
#pragma unroll
            for (int u = 0; u < 4; u++) {
                float4 fk = *(const float4*)(ksrc + kdb + u * 4);
                float4 fv = *(const float4*)(vsrc + kdb + u * 4);
                const float* ek = (const float*)&fk;
                const float* ev = (const float*)&fv;
#pragma unroll
                for (int e = 0; e < 4; e++) {
                    int d = kdb + u * 4 + e;
                    uint32_t hi, lo;
                    split_tf32(ek[e], hi, lo);
                    sm[KH_OFF + b_off(d, key, 8)] = hi;
                    sm[KL_OFF + b_off(d, key, 8)] = lo;
                    split_tf32(ev[e], hi, lo);
                    sm[VH_OFF + b_off(key, d, 8)] = hi;
                    sm[VL_OFF + b_off(key, d, 8)] = lo;
                }
            }
        }
        __syncthreads();

        // ---- scores = Q @ K^T (3xTF32) ----
        float s[2][4][4] = {};
#pragma unroll
        for (int kk = 0; kk < 8; kk++) {
            uint4 ah[2], al[2];
            uint2 bh[4], bl[4];
#pragma unroll
            for (int i = 0; i < 2; i++) {
                int ti = ((m0 >> 4) + i) * 8 + kk;
                ah[i] = ((const uint4*)(sm + QH_OFF))[ti * 32 + lane];
                al[i] = ((const uint4*)(sm + QL_OFF))[ti * 32 + lane];
            }
#pragma unroll
            for (int j = 0; j < 4; j++) {
                int tj = ((n0 >> 3) + j) * 8 + kk;
                bh[j] = ((const uint2*)(sm + KH_OFF))[tj * 32 + lane];
                bl[j] = ((const uint2*)(sm + KL_OFF))[tj * 32 + lane];
            }
#pragma unroll
            for (int i = 0; i < 2; i++)
#pragma unroll
                for (int j = 0; j < 4; j++)
                    mma3(s[i][j], ah[i], al[i], bh[j], bl[j]);
        }

        // ---- exp, accumulate l, write unnormalized weights, stage W frags ----
#pragma unroll
        for (int i = 0; i < 2; i++) {
            int r0 = m0 + i * 16 + g;
            int r1 = r0 + 8;
#pragma unroll
            for (int j = 0; j < 4; j++) {
                int cl = n0 + j * 8 + t * 2;
                float e0 = __expf(s[i][j][0]);
                float e1 = __expf(s[i][j][1]);
                float e2 = __expf(s[i][j][2]);
                float e3 = __expf(s[i][j][3]);
                l_part[i * 2 + 0] += e0 + e1;
                l_part[i * 2 + 1] += e2 + e3;
                size_t abase = ((size_t)((b * N_HEAD + h) * SEQ + q0 + r0)) * SEQ + c0 + cl;
                *(float2*)(attn + abase) = make_float2(e0, e1);
                *(float2*)(attn + abase + (size_t)8 * SEQ) = make_float2(e2, e3);
                uint32_t hi, lo;
                split_tf32(e0, hi, lo);
                sm[WH_OFF + a_off(r0, cl, 8)] = hi;     sm[WL_OFF + a_off(r0, cl, 8)] = lo;
                split_tf32(e1, hi, lo);
                sm[WH_OFF + a_off(r0, cl + 1, 8)] = hi; sm[WL_OFF + a_off(r0, cl + 1, 8)] = lo;
                split_tf32(e2, hi, lo);
                sm[WH_OFF + a_off(r1, cl, 8)] = hi;     sm[WL_OFF + a_off(r1, cl, 8)] = lo;
                split_tf32(e3, hi, lo);
                sm[WH_OFF + a_off(r1, cl + 1, 8)] = hi; sm[WL_OFF + a_off(r1, cl + 1, 8)] = lo;
            }
        }
        __syncthreads();

        // ---- context += W @ V (3xTF32) ----
#pragma unroll
        for (int kk = 0; kk < 8; kk++) {
            uint4 ah[2], al[2];
            uint2 bh[4], bl[4];
#pragma unroll
            for (int i = 0; i < 2; i++) {
                int ti = ((m0 >> 4) + i) * 8 + kk;
                ah[i] = ((const uint4*)(sm + WH_OFF))[ti * 32 + lane];
                al[i] = ((const uint4*)(sm + WL_OFF))[ti * 32 + lane];
            }
#pragma unroll
            for (int j = 0; j < 4; j++) {
                int tj = ((n0 >> 3) + j) * 8 + kk;
                bh[j] = ((const uint2*)(sm + VH_OFF))[tj * 32 + lane];
                bl[j] = ((const uint2*)(sm + VL_OFF))[tj * 32 + lane];
            }
#pragma unroll
            for (int i = 0; i < 2; i++)
#pragma unroll
                for (int j = 0; j < 4; j++)
                    mma3(cacc[i][j], ah[i], al[i], bh[j], bl[j]);
        }
    }

    // ---- reduce l across lanes (t) and warps ----
#pragma unroll
    for (int x = 0; x < 4; x++) {
        float v = l_part[x];
        v += __shfl_xor_sync(0xffffffffu, v, 1);
        v += __shfl_xor_sync(0xffffffffu, v, 2);
        if (t == 0)
            atomicAdd(&lsm[m0 + (x >> 1) * 16 + g + (x & 1) * 8], v);
    }
    __syncthreads();

    if (tid < 128)
        linv_out[(size_t)(b * N_HEAD + h) * SEQ + q0 + tid] = 1.0f / lsm[tid];

    // ---- context epilogue (normalize rows) ----
#pragma unroll
    for (int i = 0; i < 2; i++) {
        int r0 = m0 + i * 16 + g;
        int r1 = r0 + 8;
        float ri0 = 1.0f / lsm[r0];
        float ri1 = 1.0f / lsm[r1];
#pragma unroll
        for (int j = 0; j < 4; j++) {
            int col = n0 + j * 8 + t * 2;
            float* d0 = &ctx_out[(size_t)(b * SEQ + q0 + r0) * MODEL_DIM + h * HEAD_DIM + col];
            float* d1 = &ctx_out[(size_t)(b * SEQ + q0 + r1) * MODEL_DIM + h * HEAD_DIM + col];
            *(float2*)d0 = make_float2(cacc[i][j][0] * ri0, cacc[i][j][1] * ri0);
            *(float2*)d1 = make_float2(cacc[i][j][2] * ri1, cacc[i][j][3] * ri1);
        }
    }
}

// ---------------------------------------------------------------------------
// Normalize attention weights by per-row 1/l.
// ---------------------------------------------------------------------------
__global__ __launch_bounds__(256) void norm_kernel(
    float* __restrict__ attn, const float* __restrict__ linv) {
    size_t i4 = (size_t)blockIdx.x * 256 + threadIdx.x;
    float r = __ldg(&linv[i4 >> 9]);   // 2048/4 = 512 float4s per row
    float4* p = ((float4*)attn) + i4;
    float4 v = *p;
    v.x *= r; v.y *= r; v.z *= r; v.w *= r;
    *p = v;
}

// ---------------------------------------------------------------------------
// Launch
// ---------------------------------------------------------------------------
extern "C" void kernel_launch(void* const* d_in, const int* in_sizes, int n_in,
                              void* d_out, int out_size) {
    const float* q    = (const float*)d_in[0];
    const float* k    = (const float*)d_in[1];
    const float* v    = (const float*)d_in[2];
    const float* wq_w = (const float*)d_in[3];
    const float* wq_b = (const float*)d_in[4];
    const float* wk_w = (const float*)d_in[5];
    const float* wk_b = (const float*)d_in[6];
    const float* wv_w = (const float*)d_in[7];
    const float* wv_b = (const float*)d_in[8];
    const float* wo_w = (const float*)d_in[9];
    const float* wo_b = (const float*)d_in[10];

    float *qp, *kp, *vp, *ctx, *linv;
    cudaGetSymbolAddress((void**)&qp,   g_qp);
    cudaGetSymbolAddress((void**)&kp,   g_kp);
    cudaGetSymbolAddress((void**)&vp,   g_vp);
    cudaGetSymbolAddress((void**)&ctx,  g_ctx);
    cudaGetSymbolAddress((void**)&linv, g_linv);

    float* out  = (float*)d_out;
    float* attn = out + (size_t)BATCH * SEQ * MODEL_DIM;

    dim3 pgrid(MODEL_DIM / 128, ROWS_TOT / 128);   // (6, 32)
    proj3_kernel<<<pgrid, 256>>>(q, wq_w, wq_b, qp);
    proj3_kernel<<<pgrid, 256>>>(k, wk_w, wk_b, kp);
    proj3_kernel<<<pgrid, 256>>>(v, wv_w, wv_b, vp);

    cudaFuncSetAttribute(attn3_kernel,
                         cudaFuncAttributeMaxDynamicSharedMemorySize, ATTN_SMEM);
    attn3_kernel<<<dim3(SEQ / 128, N_HEAD, BATCH), 256, ATTN_SMEM>>>(
        qp, kp, vp, attn, ctx, linv);

    const int n4 = (BATCH * N_HEAD * SEQ * SEQ) / 4;   // 25165824
    norm_kernel<<<n4 / 256, 256>>>(attn, linv);

    proj3_kernel<<<pgrid, 256>>>(ctx, wo_w, wo_b, out);
}

// round 5
// speedup vs baseline: 1.7423x; 1.3807x over previous
#include <cuda_runtime.h>
#include <cstdint>
#include <cstddef>

#define MODEL_DIM 768
#define N_HEAD    12
#define HEAD_DIM  64
#define BATCH     2
#define SEQ       2048
#define ROWS_TOT  4096
#define KT_TOT    96            // 768/8
#define ELEMS     (ROWS_TOT * MODEL_DIM)   // 3145728
#define WELEMS    (MODEL_DIM * MODEL_DIM)  // 589824

// ---------------------------------------------------------------------------
// Scratch (__device__ globals)
// ---------------------------------------------------------------------------
__device__ uint32_t g_inh[3][ELEMS];   // pre-split inputs (A-frag layout) hi
__device__ uint32_t g_inl[3][ELEMS];   // lo
__device__ uint32_t g_wh[4][WELEMS];   // pre-split weights (B-frag layout) hi
__device__ uint32_t g_wl[4][WELEMS];   // lo
__device__ uint32_t g_qh[ELEMS], g_ql[ELEMS];   // Q attn A-frag layout
__device__ uint32_t g_kh[ELEMS], g_kl[ELEMS];   // K attn B-frag layout
__device__ uint32_t g_vh[ELEMS], g_vl[ELEMS];   // V attn B-frag layout
__device__ uint32_t g_ch[ELEMS], g_cl[ELEMS];   // ctx A-frag layout (for out proj)
__device__ float    g_linv[BATCH * N_HEAD * SEQ];

// ---------------------------------------------------------------------------
// TF32 + mma helpers
// ---------------------------------------------------------------------------
__device__ __forceinline__ uint32_t tf32_of(float x) {
    uint32_t u; asm("cvt.rna.tf32.f32 %0, %1;" : "=r"(u) : "f"(x)); return u;
}
__device__ __forceinline__ void split_tf32(float x, uint32_t& hi, uint32_t& lo) {
    hi = tf32_of(x);
    lo = tf32_of(x - __uint_as_float(hi));
}
__device__ __forceinline__ void mma1(float* d, const uint4& a, const uint2& b) {
    asm volatile(
        "mma.sync.aligned.m16n8k8.row.col.f32.tf32.tf32.f32 "
        "{%0,%1,%2,%3},{%4,%5,%6,%7},{%8,%9},{%0,%1,%2,%3};"
        : "+f"(d[0]), "+f"(d[1]), "+f"(d[2]), "+f"(d[3])
        : "r"(a.x), "r"(a.y), "r"(a.z), "r"(a.w), "r"(b.x), "r"(b.y));
}
__device__ __forceinline__ void mma3(float* d, const uint4& ah, const uint4& al,
                                     const uint2& bh, const uint2& bl) {
    mma1(d, ah, bh); mma1(d, ah, bl); mma1(d, al, bh);
}
__device__ __forceinline__ void cpa16(uint32_t s, const void* g) {
    asm volatile("cp.async.ca.shared.global [%0], [%1], 16;" :: "r"(s), "l"(g));
}
#define CP_COMMIT() asm volatile("cp.async.commit_group;")
#define CP_WAIT0()  asm volatile("cp.async.wait_group 0;")

// ---------------------------------------------------------------------------
// Prep: input fp32 [4096x768] -> A-frag hi/lo, layout [rowblk32][kt96][mt8][128]
// A tile 16x8: lane=(r&7)*4+(c&3), slots: (g,t),(g+8,t),(g,t+4),(g+8,t+4)
// ---------------------------------------------------------------------------
__global__ __launch_bounds__(256) void prep_a_kernel(
    const float* __restrict__ X, uint32_t* __restrict__ Ah, uint32_t* __restrict__ Al) {
    int id = blockIdx.x * 256 + threadIdx.x;     // 786432
    int lane = id & 31;
    int tile = id >> 5;                          // 24576
    int mt = tile & 7, kt = (tile >> 3) % KT_TOT, rb = tile / (KT_TOT * 8);
    int r0 = rb * 128 + mt * 16 + (lane >> 2);
    int c0 = kt * 8 + (lane & 3);
    float v0 = X[(size_t)r0 * MODEL_DIM + c0];
    float v1 = X[(size_t)(r0 + 8) * MODEL_DIM + c0];
    float v2 = X[(size_t)r0 * MODEL_DIM + c0 + 4];
    float v3 = X[(size_t)(r0 + 8) * MODEL_DIM + c0 + 4];
    uint4 h, l;
    split_tf32(v0, h.x, l.x); split_tf32(v1, h.y, l.y);
    split_tf32(v2, h.z, l.z); split_tf32(v3, h.w, l.w);
    ((uint4*)Ah)[(size_t)tile * 32 + lane] = h;
    ((uint4*)Al)[(size_t)tile * 32 + lane] = l;
}

// Prep: W fp32 [768x768] -> B-frag hi/lo, layout [colblk6][kt96][nt16][64]
// B tile 8x8 (k x n): lane=(n&7)*4+(k&3), slots: (t,g),(t+4,g)
__global__ __launch_bounds__(256) void prep_b_kernel(
    const float* __restrict__ W, uint32_t* __restrict__ Bh, uint32_t* __restrict__ Bl) {
    int id = blockIdx.x * 256 + threadIdx.x;     // 294912
    int lane = id & 31;
    int tile = id >> 5;                          // 9216
    int nt = tile & 15, kt = (tile >> 4) % KT_TOT, cb = tile / (KT_TOT * 16);
    int n = cb * 128 + nt * 8 + (lane >> 2);
    int k = kt * 8 + (lane & 3);
    float v0 = W[(size_t)n * MODEL_DIM + k];
    float v1 = W[(size_t)n * MODEL_DIM + k + 4];
    uint2 h, l;
    split_tf32(v0, h.x, l.x); split_tf32(v1, h.y, l.y);
    ((uint2*)Bh)[(size_t)tile * 32 + lane] = h;
    ((uint2*)Bl)[(size_t)tile * 32 + lane] = l;
}

// ---------------------------------------------------------------------------
// Projection GEMM (pre-split frags). Block 128x128, KC=16, 2-stage cp.async.
// 8 warps: 2m x 4n, warp tile 64x32.
// mode 0=Q(attn A-layout, *0.125), 1=K(attn B), 2=V(attn B), 3=fp32 out
// ---------------------------------------------------------------------------
__device__ __forceinline__ void scat_qkv(int mode, uint32_t* oh, uint32_t* ol,
                                         int R, int c, float v) {
    int b = R >> 11, s = R & 2047, h = c >> 6, d = c & 63;
    size_t idx;
    if (mode == 0) {          // Q: [b][h][qblk16][kt8][mt8][128]
        size_t tile = (((size_t)(b * N_HEAD + h) * 16 + (s >> 7)) * 8 + (d >> 3)) * 8
                      + ((s & 127) >> 4);
        idx = tile * 128 + (((s & 7) << 2) | (d & 3)) * 4 + ((s >> 3) & 1)
              + (((d >> 2) & 1) << 1);
    } else if (mode == 1) {   // K: [b][h][chunk32][kt8(d)][nt8(key)][64]
        size_t tile = (((size_t)(b * N_HEAD + h) * 32 + (s >> 6)) * 8 + (d >> 3)) * 8
                      + ((s & 63) >> 3);
        idx = tile * 64 + (((s & 7) << 2) | (d & 3)) * 2 + ((d >> 2) & 1);
    } else {                  // V: [b][h][chunk32][kt8(key)][nt8(d)][64]
        size_t tile = (((size_t)(b * N_HEAD + h) * 32 + (s >> 6)) * 8 + ((s & 63) >> 3)) * 8
                      + (d >> 3);
        idx = tile * 64 + (((d & 7) << 2) | (s & 3)) * 2 + ((s >> 2) & 1);
    }
    uint32_t hi, lo; split_tf32(v, hi, lo);
    oh[idx] = hi; ol[idx] = lo;
}

__global__ __launch_bounds__(256) void proj_kernel(
    const uint32_t* __restrict__ Ah, const uint32_t* __restrict__ Al,
    const uint32_t* __restrict__ Bh, const uint32_t* __restrict__ Bl,
    const float* __restrict__ bias, float* __restrict__ outF,
    uint32_t* __restrict__ oh, uint32_t* __restrict__ ol, int mode) {
    extern __shared__ uint32_t S[];   // [stage2][arr4][2048]
    const int tid = threadIdx.x;
    const int lane = tid & 31;
    const int w = tid >> 5;
    const int g = lane >> 2;
    const int t = lane & 3;
    const int cb = blockIdx.x;        // col block
    const int rb = blockIdx.y;        // row block
    const int m0 = (w >> 2) * 64;
    const int n0 = (w & 3) * 32;
    const int bm = rb * 128, bn = cb * 128;

    uint32_t sbase = (uint32_t)__cvta_generic_to_shared(S);

    auto issue = [&](int st, int it) {
        size_t aoff = ((size_t)rb * KT_TOT + it * 2) * 1024;
        size_t boff = ((size_t)cb * KT_TOT + it * 2) * 1024;
        const uint32_t* src[4] = {Ah + aoff, Al + aoff, Bh + boff, Bl + boff};
#pragma unroll
        for (int a = 0; a < 4; a++) {
            uint32_t dst = sbase + ((st * 4 + a) * 2048) * 4;
#pragma unroll
            for (int u = 0; u < 2; u++) {
                int e = (tid + u * 256) * 4;
                cpa16(dst + e * 4, src[a] + e);
            }
        }
        CP_COMMIT();
    };

    float acc[4][4][4] = {};
    issue(0, 0);

    for (int it = 0; it < KT_TOT / 2; it++) {
        int st = it & 1;
        CP_WAIT0();
        __syncthreads();
        if (it + 1 < KT_TOT / 2) issue(st ^ 1, it + 1);
        const uint32_t* sAh = S + (st * 4 + 0) * 2048;
        const uint32_t* sAl = S + (st * 4 + 1) * 2048;
        const uint32_t* sBh = S + (st * 4 + 2) * 2048;
        const uint32_t* sBl = S + (st * 4 + 3) * 2048;
#pragma unroll
        for (int kk = 0; kk < 2; kk++) {
            uint4 ah[4], al[4];
            uint2 bh[4], bl[4];
#pragma unroll
            for (int i = 0; i < 4; i++) {
                int idx = (kk * 8 + (m0 >> 4) + i) * 32 + lane;
                ah[i] = ((const uint4*)sAh)[idx];
                al[i] = ((const uint4*)sAl)[idx];
            }
#pragma unroll
            for (int j = 0; j < 4; j++) {
                int idx = (kk * 16 + (n0 >> 3) + j) * 32 + lane;
                bh[j] = ((const uint2*)sBh)[idx];
                bl[j] = ((const uint2*)sBl)[idx];
            }
#pragma unroll
            for (int i = 0; i < 4; i++)
#pragma unroll
                for (int j = 0; j < 4; j++)
                    mma3(acc[i][j], ah[i], al[i], bh[j], bl[j]);
        }
        __syncthreads();
    }

    // epilogue
#pragma unroll
    for (int j = 0; j < 4; j++) {
        int c0 = bn + n0 + j * 8 + t * 2;
        float b0 = __ldg(&bias[c0]);
        float b1 = __ldg(&bias[c0 + 1]);
#pragma unroll
        for (int i = 0; i < 4; i++) {
            int r0 = bm + m0 + i * 16 + g;
            float v00 = acc[i][j][0] + b0, v01 = acc[i][j][1] + b1;
            float v10 = acc[i][j][2] + b0, v11 = acc[i][j][3] + b1;
            if (mode == 3) {
                *(float2*)&outF[(size_t)r0 * MODEL_DIM + c0] = make_float2(v00, v01);
                *(float2*)&outF[(size_t)(r0 + 8) * MODEL_DIM + c0] = make_float2(v10, v11);
            } else {
                float sc = (mode == 0) ? 0.125f : 1.0f;
                scat_qkv(mode, oh, ol, r0, c0, v00 * sc);
                scat_qkv(mode, oh, ol, r0, c0 + 1, v01 * sc);
                scat_qkv(mode, oh, ol, r0 + 8, c0, v10 * sc);
                scat_qkv(mode, oh, ol, r0 + 8, c0 + 1, v11 * sc);
            }
        }
    }
}

// ---------------------------------------------------------------------------
// Attention. Block = (qblk of 128, h, b), 256 thr (8 warps: 4m x 2n).
// Pre-split Q/K/V fragments; W staged in-kernel.
// ---------------------------------------------------------------------------
#define QH_OFF 0
#define QL_OFF 8192
#define KH_OFF 16384
#define KL_OFF 20480
#define VH_OFF 24576
#define VL_OFF 28672
#define WH_OFF 32768
#define WL_OFF 40960
#define LS_OFF 49152
#define ATTN_SMEM ((49152 + 128) * 4)

__global__ __launch_bounds__(256, 1) void attn_kernel(
    const uint32_t* __restrict__ qh, const uint32_t* __restrict__ ql,
    const uint32_t* __restrict__ kh, const uint32_t* __restrict__ kl,
    const uint32_t* __restrict__ vh, const uint32_t* __restrict__ vl,
    float* __restrict__ attn, uint32_t* __restrict__ ch, uint32_t* __restrict__ cl,
    float* __restrict__ linv_out) {
    extern __shared__ uint32_t sm[];
    float* lsm = (float*)(sm + LS_OFF);

    const int tid = threadIdx.x;
    const int lane = tid & 31;
    const int w = tid >> 5;
    const int g = lane >> 2;
    const int t = lane & 3;
    const int b = blockIdx.z;
    const int h = blockIdx.y;
    const int q0 = blockIdx.x * 128;
    const int m0 = (w >> 1) * 32;
    const int n0 = (w & 1) * 32;

    uint32_t sbase = (uint32_t)__cvta_generic_to_shared(sm);

    // Q tile copy (one-time)
    {
        size_t qb = ((size_t)(b * N_HEAD + h) * 16 + (q0 >> 7)) * 8192;
#pragma unroll
        for (int u = 0; u < 8; u++) {
            int e = tid + u * 256;
            ((uint4*)(sm + QH_OFF))[e] = ((const uint4*)(qh + qb))[e];
            ((uint4*)(sm + QL_OFF))[e] = ((const uint4*)(ql + qb))[e];
        }
    }
    if (tid < 128) lsm[tid] = 0.0f;

    float l_part[4] = {0.f, 0.f, 0.f, 0.f};
    float cacc[2][4][4] = {};

    for (int kc = 0; kc < SEQ / 64; kc++) {
        const int c0 = kc * 64;
        __syncthreads();
        {
            size_t kb = ((size_t)(b * N_HEAD + h) * 32 + kc) * 4096;
            const uint32_t* src[4] = {kh + kb, kl + kb, vh + kb, vl + kb};
            const int off[4] = {KH_OFF, KL_OFF, VH_OFF, VL_OFF};
#pragma unroll
            for (int a = 0; a < 4; a++)
#pragma unroll
                for (int u = 0; u < 4; u++) {
                    int e = (tid + u * 256) * 4;
                    cpa16(sbase + (off[a] + e) * 4, src[a] + e);
                }
            CP_COMMIT();
            CP_WAIT0();
        }
        __syncthreads();

        // scores = Q @ K^T
        float s[2][4][4] = {};
#pragma unroll
        for (int kk = 0; kk < 8; kk++) {
            uint4 ah[2], al[2];
            uint2 bh[4], bl[4];
#pragma unroll
            for (int i = 0; i < 2; i++) {
                int idx = (kk * 8 + (m0 >> 4) + i) * 32 + lane;
                ah[i] = ((const uint4*)(sm + QH_OFF))[idx];
                al[i] = ((const uint4*)(sm + QL_OFF))[idx];
            }
#pragma unroll
            for (int j = 0; j < 4; j++) {
                int idx = (kk * 8 + (n0 >> 3) + j) * 32 + lane;
                bh[j] = ((const uint2*)(sm + KH_OFF))[idx];
                bl[j] = ((const uint2*)(sm + KL_OFF))[idx];
            }
#pragma unroll
            for (int i = 0; i < 2; i++)
#pragma unroll
                for (int j = 0; j < 4; j++)
                    mma3(s[i][j], ah[i], al[i], bh[j], bl[j]);
        }

        // exp, l accumulate, write unnormalized weights, stage W (A-frag [kt=key][mt=q])
#pragma unroll
        for (int i = 0; i < 2; i++) {
            int r0 = m0 + i * 16 + g;
            int r1 = r0 + 8;
#pragma unroll
            for (int j = 0; j < 4; j++) {
                int cL = n0 + j * 8 + t * 2;
                float e0 = __expf(s[i][j][0]);
                float e1 = __expf(s[i][j][1]);
                float e2 = __expf(s[i][j][2]);
                float e3 = __expf(s[i][j][3]);
                l_part[i * 2 + 0] += e0 + e1;
                l_part[i * 2 + 1] += e2 + e3;
                size_t ab = ((size_t)((b * N_HEAD + h) * SEQ + q0 + r0)) * SEQ + c0 + cL;
                *(float2*)(attn + ab) = make_float2(e0, e1);
                *(float2*)(attn + ab + (size_t)8 * SEQ) = make_float2(e2, e3);
                uint32_t hi, lo;
                // word(r, c) = ((c>>3)*8 + (r>>4))*128 + ((r&7)*4 + (c&3))*4
                //              + ((r>>3)&1) + ((c>>2)&1)*2
                int t0 = ((cL >> 3) * 8 + (r0 >> 4)) * 128;
                int sl0 = ((r0 >> 3) & 1) + (((cL >> 2) & 1) << 1);
                split_tf32(e0, hi, lo);
                { int wd = t0 + (((r0 & 7) << 2) | (cL & 3)) * 4 + sl0;
                  sm[WH_OFF + wd] = hi; sm[WL_OFF + wd] = lo; }
                split_tf32(e1, hi, lo);
                { int wd = t0 + (((r0 & 7) << 2) | ((cL + 1) & 3)) * 4 + sl0;
                  sm[WH_OFF + wd] = hi; sm[WL_OFF + wd] = lo; }
                int t1 = ((cL >> 3) * 8 + (r1 >> 4)) * 128;
                int sl1 = ((r1 >> 3) & 1) + (((cL >> 2) & 1) << 1);
                split_tf32(e2, hi, lo);
                { int wd = t1 + (((r1 & 7) << 2) | (cL & 3)) * 4 + sl1;
                  sm[WH_OFF + wd] = hi; sm[WL_OFF + wd] = lo; }
                split_tf32(e3, hi, lo);
                { int wd = t1 + (((r1 & 7) << 2) | ((cL + 1) & 3)) * 4 + sl1;
                  sm[WH_OFF + wd] = hi; sm[WL_OFF + wd] = lo; }
            }
        }
        __syncthreads();

        // context += W @ V
#pragma unroll
        for (int kk = 0; kk < 8; kk++) {
            uint4 ah[2], al[2];
            uint2 bh[4], bl[4];
#pragma unroll
            for (int i = 0; i < 2; i++) {
                int idx = (kk * 8 + (m0 >> 4) + i) * 32 + lane;
                ah[i] = ((const uint4*)(sm + WH_OFF))[idx];
                al[i] = ((const uint4*)(sm + WL_OFF))[idx];
            }
#pragma unroll
            for (int j = 0; j < 4; j++) {
                int idx = (kk * 8 + (n0 >> 3) + j) * 32 + lane;
                bh[j] = ((const uint2*)(sm + VH_OFF))[idx];
                bl[j] = ((const uint2*)(sm + VL_OFF))[idx];
            }
#pragma unroll
            for (int i = 0; i < 2; i++)
#pragma unroll
                for (int j = 0; j < 4; j++)
                    mma3(cacc[i][j], ah[i], al[i], bh[j], bl[j]);
        }
    }

    // reduce l
#pragma unroll
    for (int x = 0; x < 4; x++) {
        float v = l_part[x];
        v += __shfl_xor_sync(0xffffffffu, v, 1);
        v += __shfl_xor_sync(0xffffffffu, v, 2);
        if (t == 0)
            atomicAdd(&lsm[m0 + (x >> 1) * 16 + g + (x & 1) * 8], v);
    }
    __syncthreads();

    if (tid < 128)
        linv_out[(size_t)(b * N_HEAD + h) * SEQ + q0 + tid] = 1.0f / lsm[tid];

    // ctx epilogue: normalize + write into A-frag gmem for out-proj
#pragma unroll
    for (int i = 0; i < 2; i++) {
        int r0 = m0 + i * 16 + g;
        int r1 = r0 + 8;
        float ri0 = 1.0f / lsm[r0];
        float ri1 = 1.0f / lsm[r1];
#pragma unroll
        for (int j = 0; j < 4; j++) {
            int col = n0 + j * 8 + t * 2;
#pragma unroll
            for (int e = 0; e < 4; e++) {
                int rr = (e < 2) ? r0 : r1;
                float ri = (e < 2) ? ri0 : ri1;
                int cc = col + (e & 1);
                float v = cacc[i][j][e] * ri;
                int R = b * SEQ + q0 + rr;
                int C = h * HEAD_DIM + cc;
                size_t idx = (((size_t)(R >> 7) * KT_TOT + (C >> 3)) * 8 + ((R & 127) >> 4))
                             * 128 + (((R & 7) << 2) | (C & 3)) * 4 + ((R >> 3) & 1)
                             + (((C >> 2) & 1) << 1);
                uint32_t hi, lo; split_tf32(v, hi, lo);
                ch[idx] = hi; cl[idx] = lo;
            }
        }
    }
}

// ---------------------------------------------------------------------------
// Normalize weights by per-row 1/l
// ---------------------------------------------------------------------------
__global__ __launch_bounds__(256) void norm_kernel(
    float* __restrict__ attn, const float* __restrict__ linv) {
    size_t i4 = (size_t)blockIdx.x * 256 + threadIdx.x;
    float r = __ldg(&linv[i4 >> 9]);
    float4* p = ((float4*)attn) + i4;
    float4 v = *p;
    v.x *= r; v.y *= r; v.z *= r; v.w *= r;
    *p = v;
}

// ---------------------------------------------------------------------------
// Launch
// ---------------------------------------------------------------------------
extern "C" void kernel_launch(void* const* d_in, const int* in_sizes, int n_in,
                              void* d_out, int out_size) {
    const float* in_x[3]  = {(const float*)d_in[0], (const float*)d_in[1], (const float*)d_in[2]};
    const float* w_w[4]   = {(const float*)d_in[3], (const float*)d_in[5], (const float*)d_in[7],
                             (const float*)d_in[9]};
    const float* w_b[4]   = {(const float*)d_in[4], (const float*)d_in[6], (const float*)d_in[8],
                             (const float*)d_in[10]};

    uint32_t *inh[3], *inl[3], *wh[4], *wl[4];
    uint32_t *qh, *ql, *kh, *kl, *vh, *vl, *ch, *cl;
    float* linv;
    {
        uint32_t* base;
        cudaGetSymbolAddress((void**)&base, g_inh);
        for (int i = 0; i < 3; i++) inh[i] = base + (size_t)i * ELEMS;
        cudaGetSymbolAddress((void**)&base, g_inl);
        for (int i = 0; i < 3; i++) inl[i] = base + (size_t)i * ELEMS;
        cudaGetSymbolAddress((void**)&base, g_wh);
        for (int i = 0; i < 4; i++) wh[i] = base + (size_t)i * WELEMS;
        cudaGetSymbolAddress((void**)&base, g_wl);
        for (int i = 0; i < 4; i++) wl[i] = base + (size_t)i * WELEMS;
    }
    cudaGetSymbolAddress((void**)&qh, g_qh); cudaGetSymbolAddress((void**)&ql, g_ql);
    cudaGetSymbolAddress((void**)&kh, g_kh); cudaGetSymbolAddress((void**)&kl, g_kl);
    cudaGetSymbolAddress((void**)&vh, g_vh); cudaGetSymbolAddress((void**)&vl, g_vl);
    cudaGetSymbolAddress((void**)&ch, g_ch); cudaGetSymbolAddress((void**)&cl, g_cl);
    cudaGetSymbolAddress((void**)&linv, g_linv);

    float* out  = (float*)d_out;
    float* attn = out + (size_t)BATCH * SEQ * MODEL_DIM;

    static bool attr_set = false;
    if (!attr_set) {
        cudaFuncSetAttribute(proj_kernel, cudaFuncAttributeMaxDynamicSharedMemorySize, 65536);
        cudaFuncSetAttribute(attn_kernel, cudaFuncAttributeMaxDynamicSharedMemorySize, ATTN_SMEM);
        attr_set = true;
    }

    // prep
    for (int i = 0; i < 3; i++)
        prep_a_kernel<<<3072, 256>>>(in_x[i], inh[i], inl[i]);
    for (int i = 0; i < 4; i++)
        prep_b_kernel<<<1152, 256>>>(w_w[i], wh[i], wl[i]);

    dim3 pgrid(MODEL_DIM / 128, ROWS_TOT / 128);   // (6, 32)
    // Q, K, V projections -> attn fragment layouts
    proj_kernel<<<pgrid, 256, 65536>>>(inh[0], inl[0], wh[0], wl[0], w_b[0],
                                       nullptr, qh, ql, 0);
    proj_kernel<<<pgrid, 256, 65536>>>(inh[1], inl[1], wh[1], wl[1], w_b[1],
                                       nullptr, kh, kl, 1);
    proj_kernel<<<pgrid, 256, 65536>>>(inh[2], inl[2], wh[2], wl[2], w_b[2],
                                       nullptr, vh, vl, 2);

    attn_kernel<<<dim3(SEQ / 128, N_HEAD, BATCH), 256, ATTN_SMEM>>>(
        qh, ql, kh, kl, vh, vl, attn, ch, cl, linv);

    const int n4 = (BATCH * N_HEAD * SEQ * SEQ) / 4;
    norm_kernel<<<n4 / 256, 256>>>(attn, linv);

    // output projection from ctx fragments
    proj_kernel<<<pgrid, 256, 65536>>>(ch, cl, wh[3], wl[3], w_b[3],
                                       out, nullptr, nullptr, 3);
}

// round 7
// speedup vs baseline: 2.9246x; 1.6785x over previous
#include <cuda_runtime.h>
#include <cstdint>
#include <cstddef>

#define MODEL_DIM 768
#define N_HEAD    12
#define HEAD_DIM  64
#define BATCH     2
#define SEQ       2048
#define ROWS_TOT  4096
#define KT_TOT    48                       // 768 / 16 (k16 tiles)
#define AWORDS    (ROWS_TOT * MODEL_DIM / 2)   // 1572864 u32 (bf16x2 packed)
#define WWORDS    (MODEL_DIM * MODEL_DIM / 2)  // 294912

// ---------------------------------------------------------------------------
// Scratch (__device__ globals)
// ---------------------------------------------------------------------------
__device__ uint32_t g_inh[3][AWORDS], g_inl[3][AWORDS];  // inputs, A-frag
__device__ uint32_t g_wh[4][WWORDS],  g_wl[4][WWORDS];   // weights, B-frag
__device__ uint32_t g_qh[AWORDS], g_ql[AWORDS];          // Q attn A-frag
__device__ uint32_t g_kh[AWORDS], g_kl[AWORDS];          // K attn B-frag
__device__ uint32_t g_vh[AWORDS], g_vl[AWORDS];          // V attn B-frag
__device__ uint32_t g_ch[AWORDS], g_cl[AWORDS];          // ctx A-frag
__device__ float    g_linv[BATCH * N_HEAD * SEQ];

// ---------------------------------------------------------------------------
// bf16 split helpers: x = hi + lo, each bf16. Pack two k-adjacent values
// into one u32 (low 16 bits = first/even-k element).
// ---------------------------------------------------------------------------
__device__ __forceinline__ uint32_t bfround(float x) {
    return __float_as_uint(x) + 0x8000u;
}
__device__ __forceinline__ void split2(float x0, float x1,
                                       uint32_t& hw, uint32_t& lw) {
    uint32_t h0 = bfround(x0) & 0xFFFF0000u;
    uint32_t h1 = bfround(x1) & 0xFFFF0000u;
    float l0 = x0 - __uint_as_float(h0);
    float l1 = x1 - __uint_as_float(h1);
    hw = (h0 >> 16) | h1;
    lw = (bfround(l0) >> 16) | (bfround(l1) & 0xFFFF0000u);
}

// mma m16n8k16 bf16: D += A*B
__device__ __forceinline__ void mma1(float* d, const uint4& a, const uint2& b) {
    asm volatile(
        "mma.sync.aligned.m16n8k16.row.col.f32.bf16.bf16.f32 "
        "{%0,%1,%2,%3},{%4,%5,%6,%7},{%8,%9},{%0,%1,%2,%3};"
        : "+f"(d[0]), "+f"(d[1]), "+f"(d[2]), "+f"(d[3])
        : "r"(a.x), "r"(a.y), "r"(a.z), "r"(a.w), "r"(b.x), "r"(b.y));
}
__device__ __forceinline__ void mma3(float* d, const uint4& ah, const uint4& al,
                                     const uint2& bh, const uint2& bl) {
    mma1(d, ah, bh); mma1(d, ah, bl); mma1(d, al, bh);
}
__device__ __forceinline__ void cpa16(uint32_t s, const void* g) {
    asm volatile("cp.async.ca.shared.global [%0], [%1], 16;" :: "r"(s), "l"(g));
}
#define CP_COMMIT() asm volatile("cp.async.commit_group;")
#define CP_WAIT0()  asm volatile("cp.async.wait_group 0;")
#define CP_WAIT1()  asm volatile("cp.async.wait_group 1;")

// Fragment word indexing (bf16x2):
// A-tile 16m x 16k = 128 u32: word = (((r&7)<<2)|((k&7)>>1))*4 + ((r>>3)&1) + (((k>>3)&1)<<1)
// B-tile 16k x 8n  =  64 u32: word = (((n&7)<<2)|((k&7)>>1))*2 + ((k>>3)&1)

// Q: [b*h][qblk16][kt4][mt8][128]   (m=s, k=d)
__device__ __forceinline__ size_t q_idx(int R, int C) {
    int b = R >> 11, s = R & 2047, h = C >> 6, d = C & 63;
    size_t tile = (((size_t)(b * N_HEAD + h) * 16 + (s >> 7)) * 4 + (d >> 4)) * 8
                  + ((s & 127) >> 4);
    return tile * 128 + ((((s & 7) << 2) | ((d & 7) >> 1)) << 2)
           + ((s >> 3) & 1) + (((d >> 3) & 1) << 1);
}
// K: [b*h][chunk32][kt4(d)][nt8(key)][64]
__device__ __forceinline__ size_t k_idx(int R, int C) {
    int b = R >> 11, s = R & 2047, h = C >> 6, d = C & 63;
    size_t tile = (((size_t)(b * N_HEAD + h) * 32 + (s >> 6)) * 4 + (d >> 4)) * 8
                  + ((s & 63) >> 3);
    return tile * 64 + ((((s & 7) << 2) | ((d & 7) >> 1)) << 1) + ((d >> 3) & 1);
}
// V: [b*h][chunk32][kt4(key)][nt8(d)][64]  (pair along s; R even)
__device__ __forceinline__ size_t v_idx(int R, int C) {
    int b = R >> 11, s = R & 2047, h = C >> 6, d = C & 63;
    size_t tile = (((size_t)(b * N_HEAD + h) * 32 + (s >> 6)) * 4 + ((s & 63) >> 4)) * 8
                  + (d >> 3);
    return tile * 64 + ((((d & 7) << 2) | ((s & 7) >> 1)) << 1) + ((s >> 3) & 1);
}
// ctx / inputs: [rowblk32][kt48][mt8][128]
__device__ __forceinline__ size_t c_idx(int R, int C) {
    size_t tile = ((size_t)(R >> 7) * KT_TOT + (C >> 4)) * 8 + ((R & 127) >> 4);
    return tile * 128 + ((((R & 7) << 2) | ((C & 7) >> 1)) << 2)
           + ((R >> 3) & 1) + (((C >> 3) & 1) << 1);
}

// ---------------------------------------------------------------------------
// Prep: X[4096x768] fp32 -> A-frag hi/lo bf16x2
// ---------------------------------------------------------------------------
__global__ __launch_bounds__(256) void prep_a_kernel(
    const float* __restrict__ X, uint32_t* __restrict__ Ah, uint32_t* __restrict__ Al) {
    int id = blockIdx.x * 256 + threadIdx.x;        // AWORDS
    int wd = id & 127, tile = id >> 7;
    int mt = tile & 7, kt = (tile >> 3) % KT_TOT, rb = tile / (KT_TOT * 8);
    int lane = wd >> 2, slot = wd & 3;
    int r = rb * 128 + mt * 16 + (slot & 1) * 8 + (lane >> 2);
    int k = kt * 16 + ((slot >> 1) & 1) * 8 + (lane & 3) * 2;
    float x0 = X[(size_t)r * MODEL_DIM + k];
    float x1 = X[(size_t)r * MODEL_DIM + k + 1];
    uint32_t hw, lw; split2(x0, x1, hw, lw);
    Ah[id] = hw; Al[id] = lw;
}

// Prep: W[768x768] -> B-frag [colblk6][kt48][nt16][64]
__global__ __launch_bounds__(256) void prep_b_kernel(
    const float* __restrict__ W, uint32_t* __restrict__ Bh, uint32_t* __restrict__ Bl) {
    int id = blockIdx.x * 256 + threadIdx.x;        // WWORDS
    int wd = id & 63, tile = id >> 6;
    int nt = tile & 15, kt = (tile >> 4) % KT_TOT, cb = tile / (KT_TOT * 16);
    int lane = wd >> 1, slot = wd & 1;
    int n = cb * 128 + nt * 8 + (lane >> 2);
    int k = kt * 16 + slot * 8 + (lane & 3) * 2;
    float x0 = W[(size_t)n * MODEL_DIM + k];
    float x1 = W[(size_t)n * MODEL_DIM + k + 1];
    uint32_t hw, lw; split2(x0, x1, hw, lw);
    Bh[id] = hw; Bl[id] = lw;
}

// ---------------------------------------------------------------------------
// Projection GEMM (split-bf16 frags). Block 128x128, k=32/iter, 2-stage.
// mode 0=Q(*0.125), 1=K, 2=V, 3=fp32 out
// ---------------------------------------------------------------------------
__global__ __launch_bounds__(256) void proj_kernel(
    const uint32_t* __restrict__ Ah, const uint32_t* __restrict__ Al,
    const uint32_t* __restrict__ Bh, const uint32_t* __restrict__ Bl,
    const float* __restrict__ bias, float* __restrict__ outF,
    uint32_t* __restrict__ oh, uint32_t* __restrict__ ol, int mode) {
    extern __shared__ uint32_t S[];   // [stage2][arr4][2048]
    const int tid = threadIdx.x;
    const int lane = tid & 31;
    const int w = tid >> 5;
    const int g = lane >> 2;
    const int t = lane & 3;
    const int cb = blockIdx.x;
    const int rb = blockIdx.y;
    const int m0 = (w >> 2) * 64;
    const int n0 = (w & 3) * 32;
    const int bm = rb * 128, bn = cb * 128;

    uint32_t sbase = (uint32_t)__cvta_generic_to_shared(S);

    auto issue = [&](int st, int it) {
        size_t aoff = ((size_t)rb * KT_TOT + it * 2) * 1024;
        size_t boff = ((size_t)cb * KT_TOT + it * 2) * 1024;
        const uint32_t* src[4] = {Ah + aoff, Al + aoff, Bh + boff, Bl + boff};
#pragma unroll
        for (int a = 0; a < 4; a++) {
            uint32_t dst = sbase + ((st * 4 + a) * 2048) * 4;
#pragma unroll
            for (int u = 0; u < 2; u++) {
                int e = (tid + u * 256) * 4;
                cpa16(dst + e * 4, src[a] + e);
            }
        }
        CP_COMMIT();
    };

    float acc[4][4][4] = {};
    issue(0, 0);

    for (int it = 0; it < KT_TOT / 2; it++) {
        int st = it & 1;
        CP_WAIT0();
        __syncthreads();
        if (it + 1 < KT_TOT / 2) issue(st ^ 1, it + 1);
        const uint32_t* sAh = S + (st * 4 + 0) * 2048;
        const uint32_t* sAl = S + (st * 4 + 1) * 2048;
        const uint32_t* sBh = S + (st * 4 + 2) * 2048;
        const uint32_t* sBl = S + (st * 4 + 3) * 2048;
#pragma unroll
        for (int kk = 0; kk < 2; kk++) {
            uint4 ah[4], al[4];
            uint2 bh[4], bl[4];
#pragma unroll
            for (int i = 0; i < 4; i++) {
                int idx = (kk * 8 + (m0 >> 4) + i) * 32 + lane;
                ah[i] = ((const uint4*)sAh)[idx];
                al[i] = ((const uint4*)sAl)[idx];
            }
#pragma unroll
            for (int j = 0; j < 4; j++) {
                int idx = (kk * 16 + (n0 >> 3) + j) * 32 + lane;
                bh[j] = ((const uint2*)sBh)[idx];
                bl[j] = ((const uint2*)sBl)[idx];
            }
#pragma unroll
            for (int i = 0; i < 4; i++)
#pragma unroll
                for (int j = 0; j < 4; j++)
                    mma3(acc[i][j], ah[i], al[i], bh[j], bl[j]);
        }
        __syncthreads();
    }

    // epilogue
#pragma unroll
    for (int j = 0; j < 4; j++) {
        int c0 = bn + n0 + j * 8 + t * 2;
        float b0 = __ldg(&bias[c0]);
        float b1 = __ldg(&bias[c0 + 1]);
#pragma unroll
        for (int i = 0; i < 4; i++) {
            int r0 = bm + m0 + i * 16 + g;
            float sc = (mode == 0) ? 0.125f : 1.0f;
            float v00 = (acc[i][j][0] + b0) * sc, v01 = (acc[i][j][1] + b1) * sc;
            float v10 = (acc[i][j][2] + b0) * sc, v11 = (acc[i][j][3] + b1) * sc;
            if (mode == 3) {
                *(float2*)&outF[(size_t)r0 * MODEL_DIM + c0] = make_float2(v00, v01);
                *(float2*)&outF[(size_t)(r0 + 8) * MODEL_DIM + c0] = make_float2(v10, v11);
            } else if (mode == 2) {
                // pair along sequence: fetch row r0+1 values from lane g+1
                float p00 = __shfl_down_sync(0xffffffffu, v00, 4);
                float p01 = __shfl_down_sync(0xffffffffu, v01, 4);
                float p10 = __shfl_down_sync(0xffffffffu, v10, 4);
                float p11 = __shfl_down_sync(0xffffffffu, v11, 4);
                if (!(g & 1)) {
                    uint32_t hw, lw; size_t ix;
                    split2(v00, p00, hw, lw); ix = v_idx(r0, c0);         oh[ix] = hw; ol[ix] = lw;
                    split2(v01, p01, hw, lw); ix = v_idx(r0, c0 + 1);     oh[ix] = hw; ol[ix] = lw;
                    split2(v10, p10, hw, lw); ix = v_idx(r0 + 8, c0);     oh[ix] = hw; ol[ix] = lw;
                    split2(v11, p11, hw, lw); ix = v_idx(r0 + 8, c0 + 1); oh[ix] = hw; ol[ix] = lw;
                }
            } else {
                // pair along d: (c0, c0+1) owned by this thread
                uint32_t hw, lw; size_t ix;
                split2(v00, v01, hw, lw);
                ix = (mode == 0) ? q_idx(r0, c0) : k_idx(r0, c0);
                oh[ix] = hw; ol[ix] = lw;
                split2(v10, v11, hw, lw);
                ix = (mode == 0) ? q_idx(r0 + 8, c0) : k_idx(r0 + 8, c0);
                oh[ix] = hw; ol[ix] = lw;
            }
        }
    }
}

// ---------------------------------------------------------------------------
// Attention. grid (16, 12, 2), 256 thr (8 warps: 4m x 2n), KV double-buffered.
// ---------------------------------------------------------------------------
#define QH_OFF 0
#define QL_OFF 4096
#define KV_OFF 8192      // stage st: KV_OFF + st*8192; KH+0 KL+2048 VH+4096 VL+6144
#define WH_OFF 24576
#define WL_OFF 28672
#define LS_OFF 32768
#define ATTN_SMEM ((32768 + 128) * 4)     // 131584 B

__global__ __launch_bounds__(256, 1) void attn_kernel(
    const uint32_t* __restrict__ qh, const uint32_t* __restrict__ ql,
    const uint32_t* __restrict__ kh, const uint32_t* __restrict__ kl,
    const uint32_t* __restrict__ vh, const uint32_t* __restrict__ vl,
    float* __restrict__ attn, uint32_t* __restrict__ ch, uint32_t* __restrict__ cl,
    float* __restrict__ linv_out) {
    extern __shared__ uint32_t sm[];
    float* lsm = (float*)(sm + LS_OFF);

    const int tid = threadIdx.x;
    const int lane = tid & 31;
    const int w = tid >> 5;
    const int g = lane >> 2;
    const int t = lane & 3;
    const int b = blockIdx.z;
    const int h = blockIdx.y;
    const int q0 = blockIdx.x * 128;
    const int m0 = (w >> 1) * 32;
    const int n0 = (w & 1) * 32;

    uint32_t sbase = (uint32_t)__cvta_generic_to_shared(sm);

    auto issue_kv = [&](int st, int kc) {
        size_t base = ((size_t)(b * N_HEAD + h) * 32 + kc) * 2048;
        const uint32_t* src[4] = {kh + base, kl + base, vh + base, vl + base};
#pragma unroll
        for (int a = 0; a < 4; a++) {
            uint32_t dst = sbase + (KV_OFF + st * 8192 + a * 2048) * 4;
#pragma unroll
            for (int u = 0; u < 2; u++) {
                int e = (tid + u * 256) * 4;
                cpa16(dst + e * 4, src[a] + e);
            }
        }
        CP_COMMIT();
    };

    issue_kv(0, 0);

    // Q tile copy (one-time)
    {
        size_t qb = ((size_t)(b * N_HEAD + h) * 16 + (q0 >> 7)) * 4096;
#pragma unroll
        for (int u = 0; u < 4; u++) {
            int e = tid + u * 256;
            ((uint4*)(sm + QH_OFF))[e] = ((const uint4*)(qh + qb))[e];
            ((uint4*)(sm + QL_OFF))[e] = ((const uint4*)(ql + qb))[e];
        }
    }
    if (tid < 128) lsm[tid] = 0.0f;

    float l_part[4] = {0.f, 0.f, 0.f, 0.f};
    float cacc[2][4][4] = {};

    for (int kc = 0; kc < SEQ / 64; kc++) {
        const int c0 = kc * 64;
        const int st = kc & 1;
        if (kc + 1 < SEQ / 64) { issue_kv(st ^ 1, kc + 1); CP_WAIT1(); }
        else                   { CP_WAIT0(); }
        __syncthreads();

        const uint32_t* sKH = sm + KV_OFF + st * 8192;
        const uint32_t* sKL = sKH + 2048;
        const uint32_t* sVH = sKH + 4096;
        const uint32_t* sVL = sKH + 6144;

        // scores = Q @ K^T
        float s[2][4][4] = {};
#pragma unroll
        for (int kk = 0; kk < 4; kk++) {
            uint4 ah[2], al[2];
            uint2 bh[4], bl[4];
#pragma unroll
            for (int i = 0; i < 2; i++) {
                int idx = (kk * 8 + (m0 >> 4) + i) * 32 + lane;
                ah[i] = ((const uint4*)(sm + QH_OFF))[idx];
                al[i] = ((const uint4*)(sm + QL_OFF))[idx];
            }
#pragma unroll
            for (int j = 0; j < 4; j++) {
                int idx = (kk * 8 + (n0 >> 3) + j) * 32 + lane;
                bh[j] = ((const uint2*)sKH)[idx];
                bl[j] = ((const uint2*)sKL)[idx];
            }
#pragma unroll
            for (int i = 0; i < 2; i++)
#pragma unroll
                for (int j = 0; j < 4; j++)
                    mma3(s[i][j], ah[i], al[i], bh[j], bl[j]);
        }

        // exp, l accumulate, write unnormalized weights, stage W frags
#pragma unroll
        for (int i = 0; i < 2; i++) {
            int r0 = m0 + i * 16 + g;
            int r1 = r0 + 8;
#pragma unroll
            for (int j = 0; j < 4; j++) {
                int cL = n0 + j * 8 + t * 2;
                float e0 = __expf(s[i][j][0]);
                float e1 = __expf(s[i][j][1]);
                float e2 = __expf(s[i][j][2]);
                float e3 = __expf(s[i][j][3]);
                l_part[i * 2 + 0] += e0 + e1;
                l_part[i * 2 + 1] += e2 + e3;
                size_t ab = ((size_t)((b * N_HEAD + h) * SEQ + q0 + r0)) * SEQ + c0 + cL;
                *(float2*)(attn + ab) = make_float2(e0, e1);
                *(float2*)(attn + ab + (size_t)8 * SEQ) = make_float2(e2, e3);
                // W A-frag (m=q row, k=key), pair along key
                uint32_t hw, lw;
                split2(e0, e1, hw, lw);
                int wd = ((cL >> 4) * 8 + (r0 >> 4)) * 128
                         + ((((r0 & 7) << 2) | ((cL & 7) >> 1)) << 2)
                         + ((r0 >> 3) & 1) + (((cL >> 3) & 1) << 1);
                sm[WH_OFF + wd] = hw; sm[WL_OFF + wd] = lw;
                split2(e2, e3, hw, lw);
                wd = ((cL >> 4) * 8 + (r1 >> 4)) * 128
                     + ((((r1 & 7) << 2) | ((cL & 7) >> 1)) << 2)
                     + ((r1 >> 3) & 1) + (((cL >> 3) & 1) << 1);
                sm[WH_OFF + wd] = hw; sm[WL_OFF + wd] = lw;
            }
        }
        __syncthreads();

        // context += W @ V
#pragma unroll
        for (int kk = 0; kk < 4; kk++) {
            uint4 ah[2], al[2];
            uint2 bh[4], bl[4];
#pragma unroll
            for (int i = 0; i < 2; i++) {
                int idx = (kk * 8 + (m0 >> 4) + i) * 32 + lane;
                ah[i] = ((const uint4*)(sm + WH_OFF))[idx];
                al[i] = ((const uint4*)(sm + WL_OFF))[idx];
            }
#pragma unroll
            for (int j = 0; j < 4; j++) {
                int idx = (kk * 8 + (n0 >> 3) + j) * 32 + lane;
                bh[j] = ((const uint2*)sVH)[idx];
                bl[j] = ((const uint2*)sVL)[idx];
            }
#pragma unroll
            for (int i = 0; i < 2; i++)
#pragma unroll
                for (int j = 0; j < 4; j++)
                    mma3(cacc[i][j], ah[i], al[i], bh[j], bl[j]);
        }
        __syncthreads();   // protect stage st before next-iteration reissue
    }

    // reduce l
#pragma unroll
    for (int x = 0; x < 4; x++) {
        float v = l_part[x];
        v += __shfl_xor_sync(0xffffffffu, v, 1);
        v += __shfl_xor_sync(0xffffffffu, v, 2);
        if (t == 0)
            atomicAdd(&lsm[m0 + (x >> 1) * 16 + g + (x & 1) * 8], v);
    }
    __syncthreads();

    if (tid < 128)
        linv_out[(size_t)(b * N_HEAD + h) * SEQ + q0 + tid] = 1.0f / lsm[tid];

    // ctx epilogue: normalize + write A-frag for out-proj (pair along model-dim)
#pragma unroll
    for (int i = 0; i < 2; i++) {
        int r0 = m0 + i * 16 + g;
        int r1 = r0 + 8;
        float ri0 = 1.0f / lsm[r0];
        float ri1 = 1.0f / lsm[r1];
#pragma unroll
        for (int j = 0; j < 4; j++) {
            int col = n0 + j * 8 + t * 2;
            int C0 = h * HEAD_DIM + col;
            int R0 = b * SEQ + q0 + r0;
            int R1 = b * SEQ + q0 + r1;
            uint32_t hw, lw; size_t ix;
            split2(cacc[i][j][0] * ri0, cacc[i][j][1] * ri0, hw, lw);
            ix = c_idx(R0, C0); ch[ix] = hw; cl[ix] = lw;
            split2(cacc[i][j][2] * ri1, cacc[i][j][3] * ri1, hw, lw);
            ix = c_idx(R1, C0); ch[ix] = hw; cl[ix] = lw;
        }
    }
}

// ---------------------------------------------------------------------------
// Normalize weights by per-row 1/l
// ---------------------------------------------------------------------------
__global__ __launch_bounds__(256) void norm_kernel(
    float* __restrict__ attn, const float* __restrict__ linv) {
    size_t i4 = (size_t)blockIdx.x * 256 + threadIdx.x;
    float r = __ldg(&linv[i4 >> 9]);
    float4* p = ((float4*)attn) + i4;
    float4 v = *p;
    v.x *= r; v.y *= r; v.z *= r; v.w *= r;
    *p = v;
}

// ---------------------------------------------------------------------------
// Launch
// ---------------------------------------------------------------------------
extern "C" void kernel_launch(void* const* d_in, const int* in_sizes, int n_in,
                              void* d_out, int out_size) {
    const float* in_x[3] = {(const float*)d_in[0], (const float*)d_in[1], (const float*)d_in[2]};
    const float* w_w[4]  = {(const float*)d_in[3], (const float*)d_in[5], (const float*)d_in[7],
                            (const float*)d_in[9]};
    const float* w_b[4]  = {(const float*)d_in[4], (const float*)d_in[6], (const float*)d_in[8],
                            (const float*)d_in[10]};

    uint32_t *inh[3], *inl[3], *wh[4], *wl[4];
    uint32_t *qh, *ql, *kh, *kl, *vh, *vl, *ch, *cl;
    float* linv;
    {
        uint32_t* base;
        cudaGetSymbolAddress((void**)&base, g_inh);
        for (int i = 0; i < 3; i++) inh[i] = base + (size_t)i * AWORDS;
        cudaGetSymbolAddress((void**)&base, g_inl);
        for (int i = 0; i < 3; i++) inl[i] = base + (size_t)i * AWORDS;
        cudaGetSymbolAddress((void**)&base, g_wh);
        for (int i = 0; i < 4; i++) wh[i] = base + (size_t)i * WWORDS;
        cudaGetSymbolAddress((void**)&base, g_wl);
        for (int i = 0; i < 4; i++) wl[i] = base + (size_t)i * WWORDS;
    }
    cudaGetSymbolAddress((void**)&qh, g_qh); cudaGetSymbolAddress((void**)&ql, g_ql);
    cudaGetSymbolAddress((void**)&kh, g_kh); cudaGetSymbolAddress((void**)&kl, g_kl);
    cudaGetSymbolAddress((void**)&vh, g_vh); cudaGetSymbolAddress((void**)&vl, g_vl);
    cudaGetSymbolAddress((void**)&ch, g_ch); cudaGetSymbolAddress((void**)&cl, g_cl);
    cudaGetSymbolAddress((void**)&linv, g_linv);

    float* out  = (float*)d_out;
    float* attn = out + (size_t)BATCH * SEQ * MODEL_DIM;

    static bool attr_set = false;
    if (!attr_set) {
        cudaFuncSetAttribute(proj_kernel, cudaFuncAttributeMaxDynamicSharedMemorySize, 65536);
        cudaFuncSetAttribute(attn_kernel, cudaFuncAttributeMaxDynamicSharedMemorySize, ATTN_SMEM);
        attr_set = true;
    }

    // prep
    for (int i = 0; i < 3; i++)
        prep_a_kernel<<<AWORDS / 256, 256>>>(in_x[i], inh[i], inl[i]);
    for (int i = 0; i < 4; i++)
        prep_b_kernel<<<WWORDS / 256, 256>>>(w_w[i], wh[i], wl[i]);

    dim3 pgrid(MODEL_DIM / 128, ROWS_TOT / 128);   // (6, 32)
    proj_kernel<<<pgrid, 256, 65536>>>(inh[0], inl[0], wh[0], wl[0], w_b[0],
                                       nullptr, qh, ql, 0);
    proj_kernel<<<pgrid, 256, 65536>>>(inh[1], inl[1], wh[1], wl[1], w_b[1],
                                       nullptr, kh, kl, 1);
    proj_kernel<<<pgrid, 256, 65536>>>(inh[2], inl[2], wh[2], wl[2], w_b[2],
                                       nullptr, vh, vl, 2);

    attn_kernel<<<dim3(SEQ / 128, N_HEAD, BATCH), 256, ATTN_SMEM>>>(
        qh, ql, kh, kl, vh, vl, attn, ch, cl, linv);

    const int n4 = (BATCH * N_HEAD * SEQ * SEQ) / 4;
    norm_kernel<<<n4 / 256, 256>>>(attn, linv);

    proj_kernel<<<pgrid, 256, 65536>>>(ch, cl, wh[3], wl[3], w_b[3],
                                       out, nullptr, nullptr, 3);
}

// round 8
// speedup vs baseline: 3.3321x; 1.1393x over previous
#include <cuda_runtime.h>
#include <cstdint>
#include <cstddef>

#define MODEL_DIM 768
#define N_HEAD    12
#define HEAD_DIM  64
#define BATCH     2
#define SEQ       2048
#define ROWS_TOT  4096
#define KT_TOT    48                       // 768 / 16 (k16 tiles)
#define AWORDS    (ROWS_TOT * MODEL_DIM / 2)   // 1572864 u32 (bf16x2 packed)
#define WWORDS    (MODEL_DIM * MODEL_DIM / 2)  // 294912

// ---------------------------------------------------------------------------
// Scratch (__device__ globals)
// ---------------------------------------------------------------------------
__device__ uint32_t g_inh[3][AWORDS], g_inl[3][AWORDS];  // inputs, A-frag
__device__ uint32_t g_wh[4][WWORDS],  g_wl[4][WWORDS];   // weights, B-frag
__device__ uint32_t g_qh[AWORDS], g_ql[AWORDS];          // Q attn A-frag
__device__ uint32_t g_kh[AWORDS], g_kl[AWORDS];          // K attn B-frag
__device__ uint32_t g_vh[AWORDS], g_vl[AWORDS];          // V attn B-frag
__device__ uint32_t g_ch[AWORDS], g_cl[AWORDS];          // ctx A-frag
__device__ float    g_linv[BATCH * N_HEAD * SEQ];

// ---------------------------------------------------------------------------
// bf16 split helpers: x = hi + lo, each bf16. Pack two k-adjacent values
// into one u32 (low 16 bits = first/even-k element).
// ---------------------------------------------------------------------------
__device__ __forceinline__ uint32_t bfround(float x) {
    return __float_as_uint(x) + 0x8000u;
}
__device__ __forceinline__ void split2(float x0, float x1,
                                       uint32_t& hw, uint32_t& lw) {
    uint32_t h0 = bfround(x0) & 0xFFFF0000u;
    uint32_t h1 = bfround(x1) & 0xFFFF0000u;
    float l0 = x0 - __uint_as_float(h0);
    float l1 = x1 - __uint_as_float(h1);
    hw = (h0 >> 16) | h1;
    lw = (bfround(l0) >> 16) | (bfround(l1) & 0xFFFF0000u);
}

// mma m16n8k16 bf16: D += A*B
__device__ __forceinline__ void mma1(float* d, const uint4& a, const uint2& b) {
    asm volatile(
        "mma.sync.aligned.m16n8k16.row.col.f32.bf16.bf16.f32 "
        "{%0,%1,%2,%3},{%4,%5,%6,%7},{%8,%9},{%0,%1,%2,%3};"
        : "+f"(d[0]), "+f"(d[1]), "+f"(d[2]), "+f"(d[3])
        : "r"(a.x), "r"(a.y), "r"(a.z), "r"(a.w), "r"(b.x), "r"(b.y));
}
__device__ __forceinline__ void mma3(float* d, const uint4& ah, const uint4& al,
                                     const uint2& bh, const uint2& bl) {
    mma1(d, ah, bh); mma1(d, ah, bl); mma1(d, al, bh);
}
__device__ __forceinline__ void cpa16(uint32_t s, const void* g) {
    asm volatile("cp.async.ca.shared.global [%0], [%1], 16;" :: "r"(s), "l"(g));
}
#define CP_COMMIT() asm volatile("cp.async.commit_group;")
#define CP_WAIT0()  asm volatile("cp.async.wait_group 0;")
#define CP_WAIT1()  asm volatile("cp.async.wait_group 1;")

// Fragment word indexing (bf16x2):
// A-tile 16m x 16k = 128 u32; B-tile 16k x 8n = 64 u32.

// Q: [b*h][qblk16][kt4][mt8][128]   (m=s, k=d)
__device__ __forceinline__ size_t q_idx(int R, int C) {
    int b = R >> 11, s = R & 2047, h = C >> 6, d = C & 63;
    size_t tile = (((size_t)(b * N_HEAD + h) * 16 + (s >> 7)) * 4 + (d >> 4)) * 8
                  + ((s & 127) >> 4);
    return tile * 128 + ((((s & 7) << 2) | ((d & 7) >> 1)) << 2)
           + ((s >> 3) & 1) + (((d >> 3) & 1) << 1);
}
// K: [b*h][chunk32][kt4(d)][nt8(key)][64]
__device__ __forceinline__ size_t k_idx(int R, int C) {
    int b = R >> 11, s = R & 2047, h = C >> 6, d = C & 63;
    size_t tile = (((size_t)(b * N_HEAD + h) * 32 + (s >> 6)) * 4 + (d >> 4)) * 8
                  + ((s & 63) >> 3);
    return tile * 64 + ((((s & 7) << 2) | ((d & 7) >> 1)) << 1) + ((d >> 3) & 1);
}
// V: [b*h][chunk32][kt4(key)][nt8(d)][64]  (pair along s; R even)
__device__ __forceinline__ size_t v_idx(int R, int C) {
    int b = R >> 11, s = R & 2047, h = C >> 6, d = C & 63;
    size_t tile = (((size_t)(b * N_HEAD + h) * 32 + (s >> 6)) * 4 + ((s & 63) >> 4)) * 8
                  + (d >> 3);
    return tile * 64 + ((((d & 7) << 2) | ((s & 7) >> 1)) << 1) + ((s >> 3) & 1);
}
// ctx / inputs: [rowblk32][kt48][mt8][128]
__device__ __forceinline__ size_t c_idx(int R, int C) {
    size_t tile = ((size_t)(R >> 7) * KT_TOT + (C >> 4)) * 8 + ((R & 127) >> 4);
    return tile * 128 + ((((R & 7) << 2) | ((C & 7) >> 1)) << 2)
           + ((R >> 3) & 1) + (((C >> 3) & 1) << 1);
}

// ---------------------------------------------------------------------------
// Prep: X[4096x768] fp32 -> A-frag hi/lo bf16x2
// ---------------------------------------------------------------------------
__global__ __launch_bounds__(256) void prep_a_kernel(
    const float* __restrict__ X, uint32_t* __restrict__ Ah, uint32_t* __restrict__ Al) {
    int id = blockIdx.x * 256 + threadIdx.x;        // AWORDS
    int wd = id & 127, tile = id >> 7;
    int mt = tile & 7, kt = (tile >> 3) % KT_TOT, rb = tile / (KT_TOT * 8);
    int lane = wd >> 2, slot = wd & 3;
    int r = rb * 128 + mt * 16 + (slot & 1) * 8 + (lane >> 2);
    int k = kt * 16 + ((slot >> 1) & 1) * 8 + (lane & 3) * 2;
    float x0 = X[(size_t)r * MODEL_DIM + k];
    float x1 = X[(size_t)r * MODEL_DIM + k + 1];
    uint32_t hw, lw; split2(x0, x1, hw, lw);
    Ah[id] = hw; Al[id] = lw;
}

// Prep: W[768x768] -> B-frag [colblk6][kt48][nt16][64]
__global__ __launch_bounds__(256) void prep_b_kernel(
    const float* __restrict__ W, uint32_t* __restrict__ Bh, uint32_t* __restrict__ Bl) {
    int id = blockIdx.x * 256 + threadIdx.x;        // WWORDS
    int wd = id & 63, tile = id >> 6;
    int nt = tile & 15, kt = (tile >> 4) % KT_TOT, cb = tile / (KT_TOT * 16);
    int lane = wd >> 1, slot = wd & 1;
    int n = cb * 128 + nt * 8 + (lane >> 2);
    int k = kt * 16 + slot * 8 + (lane & 3) * 2;
    float x0 = W[(size_t)n * MODEL_DIM + k];
    float x1 = W[(size_t)n * MODEL_DIM + k + 1];
    uint32_t hw, lw; split2(x0, x1, hw, lw);
    Bh[id] = hw; Bl[id] = lw;
}

// ---------------------------------------------------------------------------
// Projection GEMM (split-bf16 frags). Block 128x128, k=32/iter, 2-stage.
// mode 0=Q(*0.125), 1=K, 2=V, 3=fp32 out
// ---------------------------------------------------------------------------
__global__ __launch_bounds__(256) void proj_kernel(
    const uint32_t* __restrict__ Ah, const uint32_t* __restrict__ Al,
    const uint32_t* __restrict__ Bh, const uint32_t* __restrict__ Bl,
    const float* __restrict__ bias, float* __restrict__ outF,
    uint32_t* __restrict__ oh, uint32_t* __restrict__ ol, int mode) {
    extern __shared__ uint32_t S[];   // [stage2][arr4][2048]
    const int tid = threadIdx.x;
    const int lane = tid & 31;
    const int w = tid >> 5;
    const int g = lane >> 2;
    const int t = lane & 3;
    const int cb = blockIdx.x;
    const int rb = blockIdx.y;
    const int m0 = (w >> 2) * 64;
    const int n0 = (w & 3) * 32;
    const int bm = rb * 128, bn = cb * 128;

    uint32_t sbase = (uint32_t)__cvta_generic_to_shared(S);

    auto issue = [&](int st, int it) {
        size_t aoff = ((size_t)rb * KT_TOT + it * 2) * 1024;
        size_t boff = ((size_t)cb * KT_TOT + it * 2) * 1024;
        const uint32_t* src[4] = {Ah + aoff, Al + aoff, Bh + boff, Bl + boff};
#pragma unroll
        for (int a = 0; a < 4; a++) {
            uint32_t dst = sbase + ((st * 4 + a) * 2048) * 4;
#pragma unroll
            for (int u = 0; u < 2; u++) {
                int e = (tid + u * 256) * 4;
                cpa16(dst + e * 4, src[a] + e);
            }
        }
        CP_COMMIT();
    };

    float acc[4][4][4] = {};
    issue(0, 0);

    for (int it = 0; it < KT_TOT / 2; it++) {
        int st = it & 1;
        CP_WAIT0();
        __syncthreads();
        if (it + 1 < KT_TOT / 2) issue(st ^ 1, it + 1);
        const uint32_t* sAh = S + (st * 4 + 0) * 2048;
        const uint32_t* sAl = S + (st * 4 + 1) * 2048;
        const uint32_t* sBh = S + (st * 4 + 2) * 2048;
        const uint32_t* sBl = S + (st * 4 + 3) * 2048;
#pragma unroll
        for (int kk = 0; kk < 2; kk++) {
            uint4 ah[4], al[4];
            uint2 bh[4], bl[4];
#pragma unroll
            for (int i = 0; i < 4; i++) {
                int idx = (kk * 8 + (m0 >> 4) + i) * 32 + lane;
                ah[i] = ((const uint4*)sAh)[idx];
                al[i] = ((const uint4*)sAl)[idx];
            }
#pragma unroll
            for (int j = 0; j < 4; j++) {
                int idx = (kk * 16 + (n0 >> 3) + j) * 32 + lane;
                bh[j] = ((const uint2*)sBh)[idx];
                bl[j] = ((const uint2*)sBl)[idx];
            }
#pragma unroll
            for (int i = 0; i < 4; i++)
#pragma unroll
                for (int j = 0; j < 4; j++)
                    mma3(acc[i][j], ah[i], al[i], bh[j], bl[j]);
        }
        __syncthreads();
    }

    // epilogue
#pragma unroll
    for (int j = 0; j < 4; j++) {
        int c0 = bn + n0 + j * 8 + t * 2;
        float b0 = __ldg(&bias[c0]);
        float b1 = __ldg(&bias[c0 + 1]);
#pragma unroll
        for (int i = 0; i < 4; i++) {
            int r0 = bm + m0 + i * 16 + g;
            float sc = (mode == 0) ? 0.125f : 1.0f;
            float v00 = (acc[i][j][0] + b0) * sc, v01 = (acc[i][j][1] + b1) * sc;
            float v10 = (acc[i][j][2] + b0) * sc, v11 = (acc[i][j][3] + b1) * sc;
            if (mode == 3) {
                *(float2*)&outF[(size_t)r0 * MODEL_DIM + c0] = make_float2(v00, v01);
                *(float2*)&outF[(size_t)(r0 + 8) * MODEL_DIM + c0] = make_float2(v10, v11);
            } else if (mode == 2) {
                float p00 = __shfl_down_sync(0xffffffffu, v00, 4);
                float p01 = __shfl_down_sync(0xffffffffu, v01, 4);
                float p10 = __shfl_down_sync(0xffffffffu, v10, 4);
                float p11 = __shfl_down_sync(0xffffffffu, v11, 4);
                if (!(g & 1)) {
                    uint32_t hw, lw; size_t ix;
                    split2(v00, p00, hw, lw); ix = v_idx(r0, c0);         oh[ix] = hw; ol[ix] = lw;
                    split2(v01, p01, hw, lw); ix = v_idx(r0, c0 + 1);     oh[ix] = hw; ol[ix] = lw;
                    split2(v10, p10, hw, lw); ix = v_idx(r0 + 8, c0);     oh[ix] = hw; ol[ix] = lw;
                    split2(v11, p11, hw, lw); ix = v_idx(r0 + 8, c0 + 1); oh[ix] = hw; ol[ix] = lw;
                }
            } else {
                uint32_t hw, lw; size_t ix;
                split2(v00, v01, hw, lw);
                ix = (mode == 0) ? q_idx(r0, c0) : k_idx(r0, c0);
                oh[ix] = hw; ol[ix] = lw;
                split2(v10, v11, hw, lw);
                ix = (mode == 0) ? q_idx(r0 + 8, c0) : k_idx(r0 + 8, c0);
                oh[ix] = hw; ol[ix] = lw;
            }
        }
    }
}

// ---------------------------------------------------------------------------
// Attention. grid (16, 12, 2), 256 thr.
// Warp tile: 16 q-rows x ALL 64 keys -> score accumulators ARE the W A-frags
// (in-register exp/split/pack; no W smem round trip, no cross-warp exchange).
// Smem: Q frags (32 KB) + KV double buffer (64 KB) = 96 KB -> 2 CTAs/SM.
// ---------------------------------------------------------------------------
#define QH_OFF 0
#define QL_OFF 4096
#define KV_OFF 8192      // stage st: +st*8192; KH+0 KL+2048 VH+4096 VL+6144
#define ATTN_SMEM (24576 * 4)    // 98304 B

__global__ __launch_bounds__(256, 2) void attn_kernel(
    const uint32_t* __restrict__ qh, const uint32_t* __restrict__ ql,
    const uint32_t* __restrict__ kh, const uint32_t* __restrict__ kl,
    const uint32_t* __restrict__ vh, const uint32_t* __restrict__ vl,
    float* __restrict__ attn, uint32_t* __restrict__ ch, uint32_t* __restrict__ cl,
    float* __restrict__ linv_out) {
    extern __shared__ uint32_t sm[];

    const int tid = threadIdx.x;
    const int lane = tid & 31;
    const int w = tid >> 5;          // warp = q-row tile (16 rows)
    const int g = lane >> 2;
    const int t = lane & 3;
    const int b = blockIdx.z;
    const int h = blockIdx.y;
    const int q0 = blockIdx.x * 128;

    uint32_t sbase = (uint32_t)__cvta_generic_to_shared(sm);

    auto issue_kv = [&](int st, int kc) {
        size_t base = ((size_t)(b * N_HEAD + h) * 32 + kc) * 2048;
        const uint32_t* src[4] = {kh + base, kl + base, vh + base, vl + base};
#pragma unroll
        for (int a = 0; a < 4; a++) {
            uint32_t dst = sbase + (KV_OFF + st * 8192 + a * 2048) * 4;
#pragma unroll
            for (int u = 0; u < 2; u++) {
                int e = (tid + u * 256) * 4;
                cpa16(dst + e * 4, src[a] + e);
            }
        }
        CP_COMMIT();
    };

    issue_kv(0, 0);

    // Q tile copy (one-time)
    {
        size_t qb = ((size_t)(b * N_HEAD + h) * 16 + (q0 >> 7)) * 4096;
#pragma unroll
        for (int u = 0; u < 4; u++) {
            int e = tid + u * 256;
            ((uint4*)(sm + QH_OFF))[e] = ((const uint4*)(qh + qb))[e];
            ((uint4*)(sm + QL_OFF))[e] = ((const uint4*)(ql + qb))[e];
        }
    }

    float l0 = 0.f, l1 = 0.f;        // row g / row g+8 exp-sums (partial over t)
    float ctx[8][4] = {};            // [d-group j][c0..c3]

    const int r0g = q0 + w * 16 + g;               // global q row (g)
    const size_t arow = ((size_t)((b * N_HEAD + h) * SEQ) + r0g) * SEQ;

    for (int kc = 0; kc < SEQ / 64; kc++) {
        const int c0 = kc * 64;
        const int st = kc & 1;
        __syncthreads();             // all warps done with buffer st^1 (chunk kc-1)
        if (kc + 1 < SEQ / 64) { issue_kv(st ^ 1, kc + 1); CP_WAIT1(); }
        else                   { CP_WAIT0(); }
        __syncthreads();             // stage st data visible

        const uint32_t* sKH = sm + KV_OFF + st * 8192;
        const uint32_t* sKL = sKH + 2048;
        const uint32_t* sVH = sKH + 4096;
        const uint32_t* sVL = sKH + 6144;

        // ---- scores = Q @ K^T : warp rows w*16..+15, keys 0..63 ----
        float s[8][4] = {};
#pragma unroll
        for (int kk = 0; kk < 4; kk++) {
            uint4 ah = ((const uint4*)(sm + QH_OFF))[(kk * 8 + w) * 32 + lane];
            uint4 al = ((const uint4*)(sm + QL_OFF))[(kk * 8 + w) * 32 + lane];
#pragma unroll
            for (int j = 0; j < 8; j++) {
                uint2 bh = ((const uint2*)sKH)[(kk * 8 + j) * 32 + lane];
                uint2 bl = ((const uint2*)sKL)[(kk * 8 + j) * 32 + lane];
                mma3(s[j], ah, al, bh, bl);
            }
        }

        // ---- per key-16 group: exp -> gmem write + in-register A-frag, then WV ----
#pragma unroll
        for (int kk = 0; kk < 4; kk++) {
            uint4 wah, wal;
            {
                int j = kk * 2;
                float e0 = __expf(s[j][0]);
                float e1 = __expf(s[j][1]);
                float e2 = __expf(s[j][2]);
                float e3 = __expf(s[j][3]);
                l0 += e0 + e1; l1 += e2 + e3;
                size_t ab = arow + c0 + j * 8 + t * 2;
                *(float2*)(attn + ab) = make_float2(e0, e1);
                *(float2*)(attn + ab + (size_t)8 * SEQ) = make_float2(e2, e3);
                split2(e0, e1, wah.x, wal.x);
                split2(e2, e3, wah.y, wal.y);
                j = kk * 2 + 1;
                e0 = __expf(s[j][0]); e1 = __expf(s[j][1]);
                e2 = __expf(s[j][2]); e3 = __expf(s[j][3]);
                l0 += e0 + e1; l1 += e2 + e3;
                ab = arow + c0 + j * 8 + t * 2;
                *(float2*)(attn + ab) = make_float2(e0, e1);
                *(float2*)(attn + ab + (size_t)8 * SEQ) = make_float2(e2, e3);
                split2(e0, e1, wah.z, wal.z);
                split2(e2, e3, wah.w, wal.w);
            }
            // context += W @ V for this key-16 group
#pragma unroll
            for (int j = 0; j < 8; j++) {
                uint2 bh = ((const uint2*)sVH)[(kk * 8 + j) * 32 + lane];
                uint2 bl = ((const uint2*)sVL)[(kk * 8 + j) * 32 + lane];
                mma3(ctx[j], wah, wal, bh, bl);
            }
        }
    }

    // ---- l reduce within quad (lanes differing in t) ----
    l0 += __shfl_xor_sync(0xffffffffu, l0, 1);
    l0 += __shfl_xor_sync(0xffffffffu, l0, 2);
    l1 += __shfl_xor_sync(0xffffffffu, l1, 1);
    l1 += __shfl_xor_sync(0xffffffffu, l1, 2);
    float ri0 = 1.0f / l0;
    float ri1 = 1.0f / l1;

    if (t == 0) {
        size_t lb = (size_t)(b * N_HEAD + h) * SEQ + q0 + w * 16 + g;
        linv_out[lb] = ri0;
        linv_out[lb + 8] = ri1;
    }

    // ---- ctx epilogue: normalize + write A-frag gmem for out-proj ----
#pragma unroll
    for (int j = 0; j < 8; j++) {
        int C0 = h * HEAD_DIM + j * 8 + t * 2;
        int R0 = b * SEQ + q0 + w * 16 + g;
        uint32_t hw, lw; size_t ix;
        split2(ctx[j][0] * ri0, ctx[j][1] * ri0, hw, lw);
        ix = c_idx(R0, C0); ch[ix] = hw; cl[ix] = lw;
        split2(ctx[j][2] * ri1, ctx[j][3] * ri1, hw, lw);
        ix = c_idx(R0 + 8, C0); ch[ix] = hw; cl[ix] = lw;
    }
}

// ---------------------------------------------------------------------------
// Normalize weights by per-row 1/l
// ---------------------------------------------------------------------------
__global__ __launch_bounds__(256) void norm_kernel(
    float* __restrict__ attn, const float* __restrict__ linv) {
    size_t i4 = (size_t)blockIdx.x * 256 + threadIdx.x;
    float r = __ldg(&linv[i4 >> 9]);
    float4* p = ((float4*)attn) + i4;
    float4 v = *p;
    v.x *= r; v.y *= r; v.z *= r; v.w *= r;
    *p = v;
}

// ---------------------------------------------------------------------------
// Launch
// ---------------------------------------------------------------------------
extern "C" void kernel_launch(void* const* d_in, const int* in_sizes, int n_in,
                              void* d_out, int out_size) {
    const float* in_x[3] = {(const float*)d_in[0], (const float*)d_in[1], (const float*)d_in[2]};
    const float* w_w[4]  = {(const float*)d_in[3], (const float*)d_in[5], (const float*)d_in[7],
                            (const float*)d_in[9]};
    const float* w_b[4]  = {(const float*)d_in[4], (const float*)d_in[6], (const float*)d_in[8],
                            (const float*)d_in[10]};

    uint32_t *inh[3], *inl[3], *wh[4], *wl[4];
    uint32_t *qh, *ql, *kh, *kl, *vh, *vl, *ch, *cl;
    float* linv;
    {
        uint32_t* base;
        cudaGetSymbolAddress((void**)&base, g_inh);
        for (int i = 0; i < 3; i++) inh[i] = base + (size_t)i * AWORDS;
        cudaGetSymbolAddress((void**)&base, g_inl);
        for (int i = 0; i < 3; i++) inl[i] = base + (size_t)i * AWORDS;
        cudaGetSymbolAddress((void**)&base, g_wh);
        for (int i = 0; i < 4; i++) wh[i] = base + (size_t)i * WWORDS;
        cudaGetSymbolAddress((void**)&base, g_wl);
        for (int i = 0; i < 4; i++) wl[i] = base + (size_t)i * WWORDS;
    }
    cudaGetSymbolAddress((void**)&qh, g_qh); cudaGetSymbolAddress((void**)&ql, g_ql);
    cudaGetSymbolAddress((void**)&kh, g_kh); cudaGetSymbolAddress((void**)&kl, g_kl);
    cudaGetSymbolAddress((void**)&vh, g_vh); cudaGetSymbolAddress((void**)&vl, g_vl);
    cudaGetSymbolAddress((void**)&ch, g_ch); cudaGetSymbolAddress((void**)&cl, g_cl);
    cudaGetSymbolAddress((void**)&linv, g_linv);

    float* out  = (float*)d_out;
    float* attn = out + (size_t)BATCH * SEQ * MODEL_DIM;

    static bool attr_set = false;
    if (!attr_set) {
        cudaFuncSetAttribute(proj_kernel, cudaFuncAttributeMaxDynamicSharedMemorySize, 65536);
        cudaFuncSetAttribute(attn_kernel, cudaFuncAttributeMaxDynamicSharedMemorySize, ATTN_SMEM);
        attr_set = true;
    }

    // prep
    for (int i = 0; i < 3; i++)
        prep_a_kernel<<<AWORDS / 256, 256>>>(in_x[i], inh[i], inl[i]);
    for (int i = 0; i < 4; i++)
        prep_b_kernel<<<WWORDS / 256, 256>>>(w_w[i], wh[i], wl[i]);

    dim3 pgrid(MODEL_DIM / 128, ROWS_TOT / 128);   // (6, 32)
    proj_kernel<<<pgrid, 256, 65536>>>(inh[0], inl[0], wh[0], wl[0], w_b[0],
                                       nullptr, qh, ql, 0);
    proj_kernel<<<pgrid, 256, 65536>>>(inh[1], inl[1], wh[1], wl[1], w_b[1],
                                       nullptr, kh, kl, 1);
    proj_kernel<<<pgrid, 256, 65536>>>(inh[2], inl[2], wh[2], wl[2], w_b[2],
                                       nullptr, vh, vl, 2);

    attn_kernel<<<dim3(SEQ / 128, N_HEAD, BATCH), 256, ATTN_SMEM>>>(
        qh, ql, kh, kl, vh, vl, attn, ch, cl, linv);

    const int n4 = (BATCH * N_HEAD * SEQ * SEQ) / 4;
    norm_kernel<<<n4 / 256, 256>>>(attn, linv);

    proj_kernel<<<pgrid, 256, 65536>>>(ch, cl, wh[3], wl[3], w_b[3],
                                       out, nullptr, nullptr, 3);
}

// round 11
// speedup vs baseline: 4.0233x; 1.2074x over previous
#include <cuda_runtime.h>
#include <cstdint>
#include <cstddef>

#define MODEL_DIM 768
#define N_HEAD    12
#define HEAD_DIM  64
#define BATCH     2
#define SEQ       2048
#define ROWS_TOT  4096
#define KT_TOT    48                       // 768 / 16 (k16 tiles)
#define AWORDS    (ROWS_TOT * MODEL_DIM / 2)   // 1572864 u32 (bf16x2 packed)
#define WWORDS    (MODEL_DIM * MODEL_DIM / 2)  // 294912

// ---------------------------------------------------------------------------
// Scratch (__device__ globals)
// ---------------------------------------------------------------------------
__device__ uint32_t g_inh[3][AWORDS], g_inl[3][AWORDS];  // inputs, A-frag
__device__ uint32_t g_wh[4][WWORDS],  g_wl[4][WWORDS];   // weights, B-frag
__device__ uint32_t g_qh[AWORDS], g_ql[AWORDS];          // Q attn A-frag
__device__ uint32_t g_kh[AWORDS], g_kl[AWORDS];          // K attn B-frag
__device__ uint32_t g_vh[AWORDS], g_vl[AWORDS];          // V attn B-frag
__device__ uint32_t g_ch[AWORDS], g_cl[AWORDS];          // ctx A-frag
__device__ float    g_linv[BATCH * N_HEAD * SEQ];

// ---------------------------------------------------------------------------
// bf16 split helpers
// ---------------------------------------------------------------------------
__device__ __forceinline__ uint32_t bfround(float x) {
    return __float_as_uint(x) + 0x8000u;
}
__device__ __forceinline__ void split2(float x0, float x1,
                                       uint32_t& hw, uint32_t& lw) {
    uint32_t h0 = bfround(x0) & 0xFFFF0000u;
    uint32_t h1 = bfround(x1) & 0xFFFF0000u;
    float l0 = x0 - __uint_as_float(h0);
    float l1 = x1 - __uint_as_float(h1);
    hw = (h0 >> 16) | h1;
    lw = (bfround(l0) >> 16) | (bfround(l1) & 0xFFFF0000u);
}

// mma m16n8k16 bf16: D += A*B
__device__ __forceinline__ void mma1(float* d, const uint4& a, const uint2& b) {
    asm volatile(
        "mma.sync.aligned.m16n8k16.row.col.f32.bf16.bf16.f32 "
        "{%0,%1,%2,%3},{%4,%5,%6,%7},{%8,%9},{%0,%1,%2,%3};"
        : "+f"(d[0]), "+f"(d[1]), "+f"(d[2]), "+f"(d[3])
        : "r"(a.x), "r"(a.y), "r"(a.z), "r"(a.w), "r"(b.x), "r"(b.y));
}
__device__ __forceinline__ void mma3(float* d, const uint4& ah, const uint4& al,
                                     const uint2& bh, const uint2& bl) {
    mma1(d, ah, bh); mma1(d, ah, bl); mma1(d, al, bh);
}
__device__ __forceinline__ void cpa16(uint32_t s, const void* g) {
    asm volatile("cp.async.ca.shared.global [%0], [%1], 16;" :: "r"(s), "l"(g));
}
#define CP_COMMIT() asm volatile("cp.async.commit_group;")
#define CP_WAIT0()  asm volatile("cp.async.wait_group 0;")
#define CP_WAIT1()  asm volatile("cp.async.wait_group 1;")

// Fragment word indexing (bf16x2):
// Q: [b*h][qblk16][kt4][mt8][128]   (m=s, k=d)
__device__ __forceinline__ size_t q_idx(int R, int C) {
    int b = R >> 11, s = R & 2047, h = C >> 6, d = C & 63;
    size_t tile = (((size_t)(b * N_HEAD + h) * 16 + (s >> 7)) * 4 + (d >> 4)) * 8
                  + ((s & 127) >> 4);
    return tile * 128 + ((((s & 7) << 2) | ((d & 7) >> 1)) << 2)
           + ((s >> 3) & 1) + (((d >> 3) & 1) << 1);
}
// K: [b*h][chunk32][kt4(d)][nt8(key)][64]
__device__ __forceinline__ size_t k_idx(int R, int C) {
    int b = R >> 11, s = R & 2047, h = C >> 6, d = C & 63;
    size_t tile = (((size_t)(b * N_HEAD + h) * 32 + (s >> 6)) * 4 + (d >> 4)) * 8
                  + ((s & 63) >> 3);
    return tile * 64 + ((((s & 7) << 2) | ((d & 7) >> 1)) << 1) + ((d >> 3) & 1);
}
// V: [b*h][chunk32][kt4(key)][nt8(d)][64]  (pair along s; R even)
__device__ __forceinline__ size_t v_idx(int R, int C) {
    int b = R >> 11, s = R & 2047, h = C >> 6, d = C & 63;
    size_t tile = (((size_t)(b * N_HEAD + h) * 32 + (s >> 6)) * 4 + ((s & 63) >> 4)) * 8
                  + (d >> 3);
    return tile * 64 + ((((d & 7) << 2) | ((s & 7) >> 1)) << 1) + ((s >> 3) & 1);
}
// ctx / inputs: [rowblk32][kt48][mt8][128]
__device__ __forceinline__ size_t c_idx(int R, int C) {
    size_t tile = ((size_t)(R >> 7) * KT_TOT + (C >> 4)) * 8 + ((R & 127) >> 4);
    return tile * 128 + ((((R & 7) << 2) | ((C & 7) >> 1)) << 2)
           + ((R >> 3) & 1) + (((C >> 3) & 1) << 1);
}

// ---------------------------------------------------------------------------
// Prep kernels
// ---------------------------------------------------------------------------
__global__ __launch_bounds__(256) void prep_a_kernel(
    const float* __restrict__ X, uint32_t* __restrict__ Ah, uint32_t* __restrict__ Al) {
    int id = blockIdx.x * 256 + threadIdx.x;        // AWORDS
    int wd = id & 127, tile = id >> 7;
    int mt = tile & 7, kt = (tile >> 3) % KT_TOT, rb = tile / (KT_TOT * 8);
    int lane = wd >> 2, slot = wd & 3;
    int r = rb * 128 + mt * 16 + (slot & 1) * 8 + (lane >> 2);
    int k = kt * 16 + ((slot >> 1) & 1) * 8 + (lane & 3) * 2;
    float x0 = X[(size_t)r * MODEL_DIM + k];
    float x1 = X[(size_t)r * MODEL_DIM + k + 1];
    uint32_t hw, lw; split2(x0, x1, hw, lw);
    Ah[id] = hw; Al[id] = lw;
}

__global__ __launch_bounds__(256) void prep_b_kernel(
    const float* __restrict__ W, uint32_t* __restrict__ Bh, uint32_t* __restrict__ Bl) {
    int id = blockIdx.x * 256 + threadIdx.x;        // WWORDS
    int wd = id & 63, tile = id >> 6;
    int nt = tile & 15, kt = (tile >> 4) % KT_TOT, cb = tile / (KT_TOT * 16);
    int lane = wd >> 1, slot = wd & 1;
    int n = cb * 128 + nt * 8 + (lane >> 2);
    int k = kt * 16 + slot * 8 + (lane & 3) * 2;
    float x0 = W[(size_t)n * MODEL_DIM + k];
    float x1 = W[(size_t)n * MODEL_DIM + k + 1];
    uint32_t hw, lw; split2(x0, x1, hw, lw);
    Bh[id] = hw; Bl[id] = lw;
}

// ---------------------------------------------------------------------------
// Projection GEMM (split-bf16 frags). Block 128x128, k=32/iter, 2-stage.
// mode 0=Q(*0.125), 1=K, 2=V, 3=fp32 out
// ---------------------------------------------------------------------------
__global__ __launch_bounds__(256) void proj_kernel(
    const uint32_t* __restrict__ Ah, const uint32_t* __restrict__ Al,
    const uint32_t* __restrict__ Bh, const uint32_t* __restrict__ Bl,
    const float* __restrict__ bias, float* __restrict__ outF,
    uint32_t* __restrict__ oh, uint32_t* __restrict__ ol, int mode) {
    extern __shared__ uint32_t S[];   // [stage2][arr4][2048]
    const int tid = threadIdx.x;
    const int lane = tid & 31;
    const int w = tid >> 5;
    const int g = lane >> 2;
    const int t = lane & 3;
    const int cb = blockIdx.x;
    const int rb = blockIdx.y;
    const int m0 = (w >> 2) * 64;
    const int n0 = (w & 3) * 32;
    const int bm = rb * 128, bn = cb * 128;

    uint32_t sbase = (uint32_t)__cvta_generic_to_shared(S);

    auto issue = [&](int st, int it) {
        size_t aoff = ((size_t)rb * KT_TOT + it * 2) * 1024;
        size_t boff = ((size_t)cb * KT_TOT + it * 2) * 1024;
        const uint32_t* src[4] = {Ah + aoff, Al + aoff, Bh + boff, Bl + boff};
#pragma unroll
        for (int a = 0; a < 4; a++) {
            uint32_t dst = sbase + ((st * 4 + a) * 2048) * 4;
#pragma unroll
            for (int u = 0; u < 2; u++) {
                int e = (tid + u * 256) * 4;
                cpa16(dst + e * 4, src[a] + e);
            }
        }
        CP_COMMIT();
    };

    float acc[4][4][4] = {};
    issue(0, 0);

    for (int it = 0; it < KT_TOT / 2; it++) {
        int st = it & 1;
        CP_WAIT0();
        __syncthreads();
        if (it + 1 < KT_TOT / 2) issue(st ^ 1, it + 1);
        const uint32_t* sAh = S + (st * 4 + 0) * 2048;
        const uint32_t* sAl = S + (st * 4 + 1) * 2048;
        const uint32_t* sBh = S + (st * 4 + 2) * 2048;
        const uint32_t* sBl = S + (st * 4 + 3) * 2048;
#pragma unroll
        for (int kk = 0; kk < 2; kk++) {
            uint4 ah[4], al[4];
            uint2 bh[4], bl[4];
#pragma unroll
            for (int i = 0; i < 4; i++) {
                int idx = (kk * 8 + (m0 >> 4) + i) * 32 + lane;
                ah[i] = ((const uint4*)sAh)[idx];
                al[i] = ((const uint4*)sAl)[idx];
            }
#pragma unroll
            for (int j = 0; j < 4; j++) {
                int idx = (kk * 16 + (n0 >> 3) + j) * 32 + lane;
                bh[j] = ((const uint2*)sBh)[idx];
                bl[j] = ((const uint2*)sBl)[idx];
            }
#pragma unroll
            for (int i = 0; i < 4; i++)
#pragma unroll
                for (int j = 0; j < 4; j++)
                    mma3(acc[i][j], ah[i], al[i], bh[j], bl[j]);
        }
        __syncthreads();
    }

    // epilogue
#pragma unroll
    for (int j = 0; j < 4; j++) {
        int c0 = bn + n0 + j * 8 + t * 2;
        float b0 = __ldg(&bias[c0]);
        float b1 = __ldg(&bias[c0 + 1]);
#pragma unroll
        for (int i = 0; i < 4; i++) {
            int r0 = bm + m0 + i * 16 + g;
            float sc = (mode == 0) ? 0.125f : 1.0f;
            float v00 = (acc[i][j][0] + b0) * sc, v01 = (acc[i][j][1] + b1) * sc;
            float v10 = (acc[i][j][2] + b0) * sc, v11 = (acc[i][j][3] + b1) * sc;
            if (mode == 3) {
                *(float2*)&outF[(size_t)r0 * MODEL_DIM + c0] = make_float2(v00, v01);
                *(float2*)&outF[(size_t)(r0 + 8) * MODEL_DIM + c0] = make_float2(v10, v11);
            } else if (mode == 2) {
                float p00 = __shfl_down_sync(0xffffffffu, v00, 4);
                float p01 = __shfl_down_sync(0xffffffffu, v01, 4);
                float p10 = __shfl_down_sync(0xffffffffu, v10, 4);
                float p11 = __shfl_down_sync(0xffffffffu, v11, 4);
                if (!(g & 1)) {
                    uint32_t hw, lw; size_t ix;
                    split2(v00, p00, hw, lw); ix = v_idx(r0, c0);         oh[ix] = hw; ol[ix] = lw;
                    split2(v01, p01, hw, lw); ix = v_idx(r0, c0 + 1);     oh[ix] = hw; ol[ix] = lw;
                    split2(v10, p10, hw, lw); ix = v_idx(r0 + 8, c0);     oh[ix] = hw; ol[ix] = lw;
                    split2(v11, p11, hw, lw); ix = v_idx(r0 + 8, c0 + 1); oh[ix] = hw; ol[ix] = lw;
                }
            } else {
                uint32_t hw, lw; size_t ix;
                split2(v00, v01, hw, lw);
                ix = (mode == 0) ? q_idx(r0, c0) : k_idx(r0, c0);
                oh[ix] = hw; ol[ix] = lw;
                split2(v10, v11, hw, lw);
                ix = (mode == 0) ? q_idx(r0 + 8, c0) : k_idx(r0 + 8, c0);
                oh[ix] = hw; ol[ix] = lw;
            }
        }
    }
}

// ---------------------------------------------------------------------------
// Attention. grid (16, 12, 2), 256 thr; warp = 16 q-rows x all 64 keys.
// Score accumulators ARE the W A-frags (in-register exp/split/pack).
// ---------------------------------------------------------------------------
#define QH_OFF 0
#define QL_OFF 4096
#define KV_OFF 8192      // stage st: +st*8192; KH+0 KL+2048 VH+4096 VL+6144
#define ATTN_SMEM (24576 * 4)    // 98304 B

__global__ __launch_bounds__(256, 2) void attn_kernel(
    const uint32_t* __restrict__ qh, const uint32_t* __restrict__ ql,
    const uint32_t* __restrict__ kh, const uint32_t* __restrict__ kl,
    const uint32_t* __restrict__ vh, const uint32_t* __restrict__ vl,
    float* __restrict__ attn, uint32_t* __restrict__ ch, uint32_t* __restrict__ cl,
    float* __restrict__ linv_out) {
    extern __shared__ uint32_t sm[];

    const int tid = threadIdx.x;
    const int lane = tid & 31;
    const int w = tid >> 5;
    const int g = lane >> 2;
    const int t = lane & 3;
    const int b = blockIdx.z;
    const int h = blockIdx.y;
    const int q0 = blockIdx.x * 128;

    uint32_t sbase = (uint32_t)__cvta_generic_to_shared(sm);

    auto issue_kv = [&](int st, int kc) {
        size_t base = ((size_t)(b * N_HEAD + h) * 32 + kc) * 2048;
        const uint32_t* src[4] = {kh + base, kl + base, vh + base, vl + base};
#pragma unroll
        for (int a = 0; a < 4; a++) {
            uint32_t dst = sbase + (KV_OFF + st * 8192 + a * 2048) * 4;
#pragma unroll
            for (int u = 0; u < 2; u++) {
                int e = (tid + u * 256) * 4;
                cpa16(dst + e * 4, src[a] + e);
            }
        }
        CP_COMMIT();
    };

    issue_kv(0, 0);

    {
        size_t qb = ((size_t)(b * N_HEAD + h) * 16 + (q0 >> 7)) * 4096;
#pragma unroll
        for (int u = 0; u < 4; u++) {
            int e = tid + u * 256;
            ((uint4*)(sm + QH_OFF))[e] = ((const uint4*)(qh + qb))[e];
            ((uint4*)(sm + QL_OFF))[e] = ((const uint4*)(ql + qb))[e];
        }
    }

    float l0 = 0.f, l1 = 0.f;
    float ctx[8][4] = {};

    const int r0g = q0 + w * 16 + g;
    const size_t arow = ((size_t)((b * N_HEAD + h) * SEQ) + r0g) * SEQ;

    for (int kc = 0; kc < SEQ / 64; kc++) {
        const int c0 = kc * 64;
        const int st = kc & 1;
        __syncthreads();
        if (kc + 1 < SEQ / 64) { issue_kv(st ^ 1, kc + 1); CP_WAIT1(); }
        else                   { CP_WAIT0(); }
        __syncthreads();

        const uint32_t* sKH = sm + KV_OFF + st * 8192;
        const uint32_t* sKL = sKH + 2048;
        const uint32_t* sVH = sKH + 4096;
        const uint32_t* sVL = sKH + 6144;

        float s[8][4] = {};
#pragma unroll
        for (int kk = 0; kk < 4; kk++) {
            uint4 ah = ((const uint4*)(sm + QH_OFF))[(kk * 8 + w) * 32 + lane];
            uint4 al = ((const uint4*)(sm + QL_OFF))[(kk * 8 + w) * 32 + lane];
#pragma unroll
            for (int j = 0; j < 8; j++) {
                uint2 bh = ((const uint2*)sKH)[(kk * 8 + j) * 32 + lane];
                uint2 bl = ((const uint2*)sKL)[(kk * 8 + j) * 32 + lane];
                mma3(s[j], ah, al, bh, bl);
            }
        }

#pragma unroll
        for (int kk = 0; kk < 4; kk++) {
            uint4 wah, wal;
            {
                int j = kk * 2;
                float e0 = __expf(s[j][0]);
                float e1 = __expf(s[j][1]);
                float e2 = __expf(s[j][2]);
                float e3 = __expf(s[j][3]);
                l0 += e0 + e1; l1 += e2 + e3;
                size_t ab = arow + c0 + j * 8 + t * 2;
                *(float2*)(attn + ab) = make_float2(e0, e1);
                *(float2*)(attn + ab + (size_t)8 * SEQ) = make_float2(e2, e3);
                split2(e0, e1, wah.x, wal.x);
                split2(e2, e3, wah.y, wal.y);
                j = kk * 2 + 1;
                e0 = __expf(s[j][0]); e1 = __expf(s[j][1]);
                e2 = __expf(s[j][2]); e3 = __expf(s[j][3]);
                l0 += e0 + e1; l1 += e2 + e3;
                ab = arow + c0 + j * 8 + t * 2;
                *(float2*)(attn + ab) = make_float2(e0, e1);
                *(float2*)(attn + ab + (size_t)8 * SEQ) = make_float2(e2, e3);
                split2(e0, e1, wah.z, wal.z);
                split2(e2, e3, wah.w, wal.w);
            }
#pragma unroll
            for (int j = 0; j < 8; j++) {
                uint2 bh = ((const uint2*)sVH)[(kk * 8 + j) * 32 + lane];
                uint2 bl = ((const uint2*)sVL)[(kk * 8 + j) * 32 + lane];
                mma3(ctx[j], wah, wal, bh, bl);
            }
        }
    }

    l0 += __shfl_xor_sync(0xffffffffu, l0, 1);
    l0 += __shfl_xor_sync(0xffffffffu, l0, 2);
    l1 += __shfl_xor_sync(0xffffffffu, l1, 1);
    l1 += __shfl_xor_sync(0xffffffffu, l1, 2);
    float ri0 = 1.0f / l0;
    float ri1 = 1.0f / l1;

    if (t == 0) {
        size_t lb = (size_t)(b * N_HEAD + h) * SEQ + q0 + w * 16 + g;
        linv_out[lb] = ri0;
        linv_out[lb + 8] = ri1;
    }

#pragma unroll
    for (int j = 0; j < 8; j++) {
        int C0 = h * HEAD_DIM + j * 8 + t * 2;
        int R0 = b * SEQ + q0 + w * 16 + g;
        uint32_t hw, lw; size_t ix;
        split2(ctx[j][0] * ri0, ctx[j][1] * ri0, hw, lw);
        ix = c_idx(R0, C0); ch[ix] = hw; cl[ix] = lw;
        split2(ctx[j][2] * ri1, ctx[j][3] * ri1, hw, lw);
        ix = c_idx(R0 + 8, C0); ch[ix] = hw; cl[ix] = lw;
    }
}

// ---------------------------------------------------------------------------
// Normalize weights by per-row 1/l
// ---------------------------------------------------------------------------
__global__ __launch_bounds__(256) void norm_kernel(
    float* __restrict__ attn, const float* __restrict__ linv) {
    size_t i4 = (size_t)blockIdx.x * 256 + threadIdx.x;
    float r = __ldg(&linv[i4 >> 9]);
    float4* p = ((float4*)attn) + i4;
    float4 v = *p;
    v.x *= r; v.y *= r; v.z *= r; v.w *= r;
    *p = v;
}

// ---------------------------------------------------------------------------
// Launch — forked-stream graph:
//   s0: prepA(q), prepB(wq), projQ ─┐
//   s1: prepA(k), prepB(wk), projK ─┼─ attn ──┬─ s1: norm ──┐
//   s2: prepA(v), prepB(wv), projV ─┘         └─ s0: projO ─┴─ join
//   s3: prepB(wo) ────────────────────────────────┘
// ---------------------------------------------------------------------------
extern "C" void kernel_launch(void* const* d_in, const int* in_sizes, int n_in,
                              void* d_out, int out_size) {
    const float* in_x[3] = {(const float*)d_in[0], (const float*)d_in[1], (const float*)d_in[2]};
    const float* w_w[4]  = {(const float*)d_in[3], (const float*)d_in[5], (const float*)d_in[7],
                            (const float*)d_in[9]};
    const float* w_b[4]  = {(const float*)d_in[4], (const float*)d_in[6], (const float*)d_in[8],
                            (const float*)d_in[10]};

    uint32_t *inh[3], *inl[3], *wh[4], *wl[4];
    uint32_t *qh, *ql, *kh, *kl, *vh, *vl, *ch, *cl;
    float* linv;
    {
        uint32_t* base;
        cudaGetSymbolAddress((void**)&base, g_inh);
        for (int i = 0; i < 3; i++) inh[i] = base + (size_t)i * AWORDS;
        cudaGetSymbolAddress((void**)&base, g_inl);
        for (int i = 0; i < 3; i++) inl[i] = base + (size_t)i * AWORDS;
        cudaGetSymbolAddress((void**)&base, g_wh);
        for (int i = 0; i < 4; i++) wh[i] = base + (size_t)i * WWORDS;
        cudaGetSymbolAddress((void**)&base, g_wl);
        for (int i = 0; i < 4; i++) wl[i] = base + (size_t)i * WWORDS;
    }
    cudaGetSymbolAddress((void**)&qh, g_qh); cudaGetSymbolAddress((void**)&ql, g_ql);
    cudaGetSymbolAddress((void**)&kh, g_kh); cudaGetSymbolAddress((void**)&kl, g_kl);
    cudaGetSymbolAddress((void**)&vh, g_vh); cudaGetSymbolAddress((void**)&vl, g_vl);
    cudaGetSymbolAddress((void**)&ch, g_ch); cudaGetSymbolAddress((void**)&cl, g_cl);
    cudaGetSymbolAddress((void**)&linv, g_linv);

    float* out  = (float*)d_out;
    float* attn = out + (size_t)BATCH * SEQ * MODEL_DIM;

    static cudaStream_t s1, s2, s3;
    static cudaEvent_t e0, ek, ev, ewo, ea, en;
    static bool init_done = false;
    if (!init_done) {
        cudaFuncSetAttribute(proj_kernel, cudaFuncAttributeMaxDynamicSharedMemorySize, 65536);
        cudaFuncSetAttribute(attn_kernel, cudaFuncAttributeMaxDynamicSharedMemorySize, ATTN_SMEM);
        cudaStreamCreateWithFlags(&s1, cudaStreamNonBlocking);
        cudaStreamCreateWithFlags(&s2, cudaStreamNonBlocking);
        cudaStreamCreateWithFlags(&s3, cudaStreamNonBlocking);
        cudaEventCreateWithFlags(&e0,  cudaEventDisableTiming);
        cudaEventCreateWithFlags(&ek,  cudaEventDisableTiming);
        cudaEventCreateWithFlags(&ev,  cudaEventDisableTiming);
        cudaEventCreateWithFlags(&ewo, cudaEventDisableTiming);
        cudaEventCreateWithFlags(&ea,  cudaEventDisableTiming);
        cudaEventCreateWithFlags(&en,  cudaEventDisableTiming);
        init_done = true;
    }

    cudaStream_t s0 = 0;
    dim3 pgrid(MODEL_DIM / 128, ROWS_TOT / 128);   // (6, 32)

    // fork
    cudaEventRecord(e0, s0);
    cudaStreamWaitEvent(s1, e0, 0);
    cudaStreamWaitEvent(s2, e0, 0);
    cudaStreamWaitEvent(s3, e0, 0);

    // s0: Q chain
    prep_a_kernel<<<AWORDS / 256, 256, 0, s0>>>(in_x[0], inh[0], inl[0]);
    prep_b_kernel<<<WWORDS / 256, 256, 0, s0>>>(w_w[0], wh[0], wl[0]);
    proj_kernel<<<pgrid, 256, 65536, s0>>>(inh[0], inl[0], wh[0], wl[0], w_b[0],
                                           nullptr, qh, ql, 0);
    // s1: K chain
    prep_a_kernel<<<AWORDS / 256, 256, 0, s1>>>(in_x[1], inh[1], inl[1]);
    prep_b_kernel<<<WWORDS / 256, 256, 0, s1>>>(w_w[1], wh[1], wl[1]);
    proj_kernel<<<pgrid, 256, 65536, s1>>>(inh[1], inl[1], wh[1], wl[1], w_b[1],
                                           nullptr, kh, kl, 1);
    cudaEventRecord(ek, s1);
    // s2: V chain
    prep_a_kernel<<<AWORDS / 256, 256, 0, s2>>>(in_x[2], inh[2], inl[2]);
    prep_b_kernel<<<WWORDS / 256, 256, 0, s2>>>(w_w[2], wh[2], wl[2]);
    proj_kernel<<<pgrid, 256, 65536, s2>>>(inh[2], inl[2], wh[2], wl[2], w_b[2],
                                           nullptr, vh, vl, 2);
    cudaEventRecord(ev, s2);
    // s3: wo prep
    prep_b_kernel<<<WWORDS / 256, 256, 0, s3>>>(w_w[3], wh[3], wl[3]);
    cudaEventRecord(ewo, s3);

    // join K,V -> attn on s0
    cudaStreamWaitEvent(s0, ek, 0);
    cudaStreamWaitEvent(s0, ev, 0);
    attn_kernel<<<dim3(SEQ / 128, N_HEAD, BATCH), 256, ATTN_SMEM, s0>>>(
        qh, ql, kh, kl, vh, vl, attn, ch, cl, linv);
    cudaEventRecord(ea, s0);

    // s1: norm (parallel with out-proj)
    cudaStreamWaitEvent(s1, ea, 0);
    const int n4 = (BATCH * N_HEAD * SEQ * SEQ) / 4;
    norm_kernel<<<n4 / 256, 256, 0, s1>>>(attn, linv);
    cudaEventRecord(en, s1);

    // s0: output projection
    cudaStreamWaitEvent(s0, ewo, 0);
    proj_kernel<<<pgrid, 256, 65536, s0>>>(ch, cl, wh[3], wl[3], w_b[3],
                                           out, nullptr, nullptr, 3);

    // join norm back into s0
    cudaStreamWaitEvent(s0, en, 0);
}